// round 1
// baseline (speedup 1.0000x reference)
#include <cuda_runtime.h>
#include <cstdint>

#define BATCH 2
#define SEQ 2048
#define DMODEL 1024
#define NH 16
#define HD 64
#define FEAT 16
#define FDIM 153           // 1 + 16 + 136
#define NCHUNK 16
#define CHUNKSZ 128
#define ROWS (BATCH*SEQ)          // 4096
#define HROWS (BATCH*SEQ*NH)      // 131072

// ------------------------- scratch (static device memory) -------------------
__device__ float g_h[ROWS*DMODEL];
__device__ float g_q[ROWS*DMODEL];
__device__ float g_k[ROWS*DMODEL];
__device__ float g_v[ROWS*DMODEL];
__device__ float g_qf[HROWS*FEAT];
__device__ float g_kf[HROWS*FEAT];
__device__ float g_qphi[(size_t)HROWS*FDIM];
__device__ float g_kphi[(size_t)HROWS*FDIM];
__device__ float g_ckv[(size_t)BATCH*NH*NCHUNK*FDIM*HD];
__device__ float g_cks[(size_t)BATCH*NH*NCHUNK*FDIM];
__device__ float g_cat[(size_t)ROWS*2*DMODEL];

// ------------------------------- RMSNorm ------------------------------------
__global__ void rmsnorm_kernel(const float* __restrict__ x,
                               const float* __restrict__ w,
                               float* __restrict__ h) {
    int row = blockIdx.x;
    const float* xr = x + (size_t)row * DMODEL;
    float s = 0.f;
    for (int i = threadIdx.x; i < DMODEL; i += 256) { float v = xr[i]; s += v * v; }
    __shared__ float red[8];
    #pragma unroll
    for (int o = 16; o > 0; o >>= 1) s += __shfl_xor_sync(0xffffffffu, s, o);
    if ((threadIdx.x & 31) == 0) red[threadIdx.x >> 5] = s;
    __syncthreads();
    if (threadIdx.x < 8) {
        float v = red[threadIdx.x];
        #pragma unroll
        for (int o = 4; o > 0; o >>= 1) v += __shfl_xor_sync(0xffu, v, o);
        if (threadIdx.x == 0) red[0] = v;
    }
    __syncthreads();
    float rs = rsqrtf(red[0] / (float)DMODEL + 1e-6f);
    float* hr = h + (size_t)row * DMODEL;
    for (int i = threadIdx.x; i < DMODEL; i += 256) hr[i] = xr[i] * rs * w[i];
}

// ------------------------------- SGEMM 128x128x8 -----------------------------
// C[M,N] = A[M,K] @ B[K,N] (+ residual). All dims multiples of 128/8.
__global__ void sgemm128(const float* __restrict__ A, const float* __restrict__ B,
                         float* __restrict__ C, const float* __restrict__ residual,
                         int M, int N, int K) {
    __shared__ float As[8][128];
    __shared__ float Bs[8][128];
    int tid = threadIdx.x;
    int bm = blockIdx.y * 128, bn = blockIdx.x * 128;
    int aRow = tid >> 1, aCol = (tid & 1) * 4;
    int bRow = tid >> 5, bCol = (tid & 31) * 4;
    int tx = tid & 15, ty = tid >> 4;
    float acc[8][8];
    #pragma unroll
    for (int i = 0; i < 8; i++)
        #pragma unroll
        for (int j = 0; j < 8; j++) acc[i][j] = 0.f;

    for (int k0 = 0; k0 < K; k0 += 8) {
        float4 av = *(const float4*)(A + (size_t)(bm + aRow) * K + k0 + aCol);
        As[aCol + 0][aRow] = av.x; As[aCol + 1][aRow] = av.y;
        As[aCol + 2][aRow] = av.z; As[aCol + 3][aRow] = av.w;
        float4 bv = *(const float4*)(B + (size_t)(k0 + bRow) * N + bn + bCol);
        *(float4*)(&Bs[bRow][bCol]) = bv;
        __syncthreads();
        #pragma unroll
        for (int kk = 0; kk < 8; kk++) {
            float ar[8], br[8];
            #pragma unroll
            for (int i = 0; i < 8; i++) ar[i] = As[kk][ty * 8 + i];
            #pragma unroll
            for (int j = 0; j < 8; j++) br[j] = Bs[kk][tx * 8 + j];
            #pragma unroll
            for (int i = 0; i < 8; i++)
                #pragma unroll
                for (int j = 0; j < 8; j++) acc[i][j] += ar[i] * br[j];
        }
        __syncthreads();
    }
    #pragma unroll
    for (int i = 0; i < 8; i++) {
        int r = bm + ty * 8 + i;
        #pragma unroll
        for (int j = 0; j < 8; j += 4) {
            int c = bn + tx * 8 + j;
            float4 o;
            o.x = acc[i][j]; o.y = acc[i][j + 1]; o.z = acc[i][j + 2]; o.w = acc[i][j + 3];
            if (residual) {
                float4 rr = *(const float4*)(residual + (size_t)r * N + c);
                o.x += rr.x; o.y += rr.y; o.z += rr.z; o.w += rr.w;
            }
            *(float4*)(C + (size_t)r * N + c) = o;
        }
    }
}

// ---------------------- per-head 64 -> 16 projection -------------------------
// Q viewed as (HROWS, 64), W (64,16), out (HROWS,16). 16 rows per block.
__global__ void feat_proj(const float* __restrict__ Q, const float* __restrict__ W,
                          float* __restrict__ out) {
    __shared__ float Ws[64 * 16];
    __shared__ float Rs[16][64];
    for (int i = threadIdx.x; i < 64 * 16; i += 256) Ws[i] = W[i];
    int r0 = blockIdx.x * 16;
    for (int i = threadIdx.x; i < 16 * 64; i += 256)
        Rs[i >> 6][i & 63] = Q[(size_t)(r0 + (i >> 6)) * 64 + (i & 63)];
    __syncthreads();
    int lr = threadIdx.x >> 4, c = threadIdx.x & 15;
    float acc = 0.f;
    #pragma unroll
    for (int kk = 0; kk < 64; kk++) acc += Rs[lr][kk] * Ws[kk * 16 + c];
    out[(size_t)(r0 + lr) * 16 + c] = acc;
}

// ----------------------------- Taylor feature map ----------------------------
__global__ void taylor_phi(const float* __restrict__ f, float* __restrict__ phi, int rows) {
    int r = blockIdx.x * blockDim.x + threadIdx.x;
    if (r >= rows) return;
    float x[16];
    const float* fr = f + (size_t)r * 16;
    #pragma unroll
    for (int i = 0; i < 16; i++) x[i] = fr[i];
    float* p = phi + (size_t)r * FDIM;
    p[0] = 1.f;
    #pragma unroll
    for (int i = 0; i < 16; i++) p[1 + i] = x[i];
    const float inv = 0.70710678118654752440f;
    int idx = 17;
    #pragma unroll
    for (int i = 0; i < 16; i++) {
        p[idx++] = 0.5f * x[i] * x[i];
        #pragma unroll
        for (int j = i + 1; j < 16; j++) p[idx++] = inv * x[i] * x[j];
    }
}

// --------------------- pass A: per-chunk KV / Ksum sums ----------------------
__global__ void chunk_kv_kernel(const float* __restrict__ kphi, const float* __restrict__ v,
                                float* __restrict__ ckv, float* __restrict__ cks) {
    int bhc = blockIdx.x;                 // ((b*NH+h)*NCHUNK + c)
    int c = bhc & 15; int bh = bhc >> 4;
    int b = bh >> 4, hh = bh & 15;
    extern __shared__ float sm[];
    float* ks_s = sm;                     // 128*153
    float* vs_s = sm + 128 * FDIM;        // 128*64
    size_t tokbase = (size_t)(b * SEQ + c * CHUNKSZ) * NH + hh;
    for (int i = threadIdx.x; i < 128 * FDIM; i += 256) {
        int s = i / FDIM, f = i % FDIM;
        ks_s[i] = kphi[(tokbase + (size_t)s * NH) * FDIM + f];
    }
    for (int i = threadIdx.x; i < 128 * 64; i += 256) {
        int s = i >> 6, d = i & 63;
        vs_s[i] = v[(tokbase + (size_t)s * NH) * HD + d];
    }
    __syncthreads();
    for (int idx = threadIdx.x; idx < FDIM * 64; idx += 256) {
        int f = idx >> 6, d = idx & 63;
        float acc = 0.f;
        for (int s = 0; s < 128; s++) acc += ks_s[s * FDIM + f] * vs_s[s * 64 + d];
        ckv[(size_t)bhc * FDIM * 64 + idx] = acc;
    }
    for (int f = threadIdx.x; f < FDIM; f += 256) {
        float acc = 0.f;
        for (int s = 0; s < 128; s++) acc += ks_s[s * FDIM + f];
        cks[(size_t)bhc * FDIM + f] = acc;
    }
}

// --------------------- pass B: exclusive prefix over chunks ------------------
__global__ void prefix_kv(float* __restrict__ ckv, float* __restrict__ cks) {
    int idx = blockIdx.x * blockDim.x + threadIdx.x;
    const int FD = FDIM * 64;
    if (idx < 32 * FD) {
        int bh = idx / FD, fd = idx % FD;
        float run = 0.f;
        for (int c = 0; c < NCHUNK; c++) {
            size_t o = ((size_t)bh * NCHUNK + c) * FD + fd;
            float cur = ckv[o]; ckv[o] = run; run += cur;
        }
    }
    if (idx < 32 * FDIM) {
        int bh = idx / FDIM, f = idx % FDIM;
        float run = 0.f;
        for (int c = 0; c < NCHUNK; c++) {
            size_t o = ((size_t)bh * NCHUNK + c) * FDIM + f;
            float cur = cks[o]; cks[o] = run; run += cur;
        }
    }
}

// --------------------- pass C: per-chunk linear attention --------------------
__global__ void lin_attn_chunk(const float* __restrict__ qphi, const float* __restrict__ kphi,
                               const float* __restrict__ vv, const float* __restrict__ ckv,
                               const float* __restrict__ cks, float* __restrict__ cat) {
    int bhc = blockIdx.x; int c = bhc & 15; int bh = bhc >> 4;
    int b = bh >> 4, hh = bh & 15;
    extern __shared__ float sm[];
    float* As  = sm;                 // 128*128
    float* Qs  = As + 128 * 128;     // 16*128
    float* Ks  = Qs + 16 * 128;      // 16*128
    float* KVs = Ks + 16 * 128;      // 16*64
    float* KSs = KVs + 16 * 64;      // 16
    float* Vs  = KSs + 16;           // 128*64
    float* Zs  = Vs + 128 * 64;      // 128
    int tid = threadIdx.x; int tx = tid & 15, ty = tid >> 4;
    float acc[8][8], y[8][4], zq[8];
    #pragma unroll
    for (int i = 0; i < 8; i++) {
        zq[i] = 0.f;
        #pragma unroll
        for (int j = 0; j < 8; j++) acc[i][j] = 0.f;
        #pragma unroll
        for (int j = 0; j < 4; j++) y[i][j] = 0.f;
    }
    size_t tokbase = (size_t)(b * SEQ + c * CHUNKSZ) * NH + hh;
    const float* kvb = ckv + (size_t)bhc * FDIM * 64;
    const float* ksb = cks + (size_t)bhc * FDIM;

    for (int f0 = 0; f0 < FDIM; f0 += 16) {
        int ft = min(16, FDIM - f0);
        for (int i = tid; i < 128 * 16; i += 256) {
            int rr = i >> 4, kk = i & 15;
            float a = 0.f, bb = 0.f;
            if (kk < ft) {
                size_t ro = (tokbase + (size_t)rr * NH) * FDIM + f0 + kk;
                a = qphi[ro]; bb = kphi[ro];
            }
            Qs[kk * 128 + rr] = a; Ks[kk * 128 + rr] = bb;
        }
        for (int i = tid; i < 16 * 64; i += 256) {
            int kk = i >> 6, d = i & 63;
            KVs[i] = (kk < ft) ? kvb[(size_t)(f0 + kk) * 64 + d] : 0.f;
        }
        if (tid < 16) KSs[tid] = (tid < ft) ? ksb[f0 + tid] : 0.f;
        __syncthreads();
        for (int kk = 0; kk < ft; kk++) {
            float ar[8], br[8], kvr[4];
            #pragma unroll
            for (int i = 0; i < 8; i++) ar[i] = Qs[kk * 128 + ty * 8 + i];
            #pragma unroll
            for (int j = 0; j < 8; j++) br[j] = Ks[kk * 128 + tx * 8 + j];
            #pragma unroll
            for (int j = 0; j < 4; j++) kvr[j] = KVs[kk * 64 + tx * 4 + j];
            float kss = KSs[kk];
            #pragma unroll
            for (int i = 0; i < 8; i++) {
                #pragma unroll
                for (int j = 0; j < 8; j++) acc[i][j] += ar[i] * br[j];
                #pragma unroll
                for (int j = 0; j < 4; j++) y[i][j] += ar[i] * kvr[j];
                zq[i] += ar[i] * kss;
            }
        }
        __syncthreads();
    }
    // masked A -> smem
    #pragma unroll
    for (int i = 0; i < 8; i++) {
        int cr = ty * 8 + i;
        #pragma unroll
        for (int j = 0; j < 8; j++) {
            int s = tx * 8 + j;
            As[cr * 128 + s] = (s <= cr) ? acc[i][j] : 0.f;
        }
    }
    for (int i = tid; i < 128 * 64; i += 256) {
        int s = i >> 6, d = i & 63;
        Vs[i] = vv[(tokbase + (size_t)s * NH) * HD + d];
    }
    __syncthreads();
    if (tx == 0) {
        #pragma unroll
        for (int i = 0; i < 8; i++) {
            int cr = ty * 8 + i;
            float z = zq[i];
            for (int s = 0; s <= cr; s++) z += As[cr * 128 + s];
            Zs[cr] = z + 1e-6f;
        }
    }
    __syncthreads();
    for (int s = 0; s < 128; s++) {
        float av[8], vr[4];
        #pragma unroll
        for (int i = 0; i < 8; i++) av[i] = As[(ty * 8 + i) * 128 + s];
        #pragma unroll
        for (int j = 0; j < 4; j++) vr[j] = Vs[s * 64 + tx * 4 + j];
        #pragma unroll
        for (int i = 0; i < 8; i++)
            #pragma unroll
            for (int j = 0; j < 4; j++) y[i][j] += av[i] * vr[j];
    }
    #pragma unroll
    for (int i = 0; i < 8; i++) {
        int cr = ty * 8 + i;
        float invz = 1.f / Zs[cr];
        size_t row = (size_t)b * SEQ + c * CHUNKSZ + cr;
        #pragma unroll
        for (int j = 0; j < 4; j++)
            cat[row * (2 * DMODEL) + hh * HD + tx * 4 + j] = y[i][j] * invz;
    }
}

// ------------------------- sliding-window attention --------------------------
__global__ void swa_kernel(const float* __restrict__ q, const float* __restrict__ k,
                           const float* __restrict__ v, float* __restrict__ cat) {
    int id = blockIdx.x;
    int hh = id & 15; int bt = id >> 4;
    int t = bt & 2047; int b = bt >> 11;
    __shared__ float qs[64];
    __shared__ float sc[65];
    __shared__ float red[1];
    int tid = threadIdx.x;
    qs[tid] = q[((size_t)bt * NH + hh) * HD + tid];
    __syncthreads();
    int lo = t - 64;
    for (int j = tid; j < 65; j += 64) {
        int s = lo + j;
        float val = -1e30f;
        if (s >= 0) {
            const float* kr = k + ((size_t)(b * SEQ + s) * NH + hh) * HD;
            float d = 0.f;
            #pragma unroll
            for (int e = 0; e < 64; e++) d += qs[e] * kr[e];
            val = d * 0.125f;
        }
        sc[j] = val;
    }
    __syncthreads();
    if (tid == 0) {
        float mx = -1e30f;
        for (int j = 0; j < 65; j++) mx = fmaxf(mx, sc[j]);
        float sum = 0.f;
        for (int j = 0; j < 65; j++) { float e = __expf(sc[j] - mx); sc[j] = e; sum += e; }
        red[0] = 1.f / sum;
    }
    __syncthreads();
    float inv = red[0];
    float accv = 0.f;
    for (int j = 0; j < 65; j++) {
        int s = lo + j;
        if (s >= 0) accv += sc[j] * v[((size_t)(b * SEQ + s) * NH + hh) * HD + tid];
    }
    cat[(size_t)bt * (2 * DMODEL) + DMODEL + hh * HD + tid] = accv * inv;
}

// ---------------------------------- launch -----------------------------------
extern "C" void kernel_launch(void* const* d_in, const int* in_sizes, int n_in,
                              void* d_out, int out_size) {
    const float* x      = (const float*)d_in[0];
    const float* norm_w = (const float*)d_in[1];
    const float* Wq     = (const float*)d_in[2];
    const float* Wk     = (const float*)d_in[3];
    const float* Wv     = (const float*)d_in[4];
    const float* Wqf    = (const float*)d_in[5];
    const float* Wkf    = (const float*)d_in[6];
    const float* Wout   = (const float*)d_in[7];
    float* out = (float*)d_out;

    float *h, *q, *k, *v, *qf, *kf, *qphi, *kphi, *ckv, *cks, *cat;
    cudaGetSymbolAddress((void**)&h,    g_h);
    cudaGetSymbolAddress((void**)&q,    g_q);
    cudaGetSymbolAddress((void**)&k,    g_k);
    cudaGetSymbolAddress((void**)&v,    g_v);
    cudaGetSymbolAddress((void**)&qf,   g_qf);
    cudaGetSymbolAddress((void**)&kf,   g_kf);
    cudaGetSymbolAddress((void**)&qphi, g_qphi);
    cudaGetSymbolAddress((void**)&kphi, g_kphi);
    cudaGetSymbolAddress((void**)&ckv,  g_ckv);
    cudaGetSymbolAddress((void**)&cks,  g_cks);
    cudaGetSymbolAddress((void**)&cat,  g_cat);

    const int smemA = (128 * FDIM + 128 * 64) * 4;                       // 111104
    const int smemC = (128*128 + 16*128*2 + 16*64 + 16 + 128*64 + 128) * 4; // 119360
    cudaFuncSetAttribute(chunk_kv_kernel, cudaFuncAttributeMaxDynamicSharedMemorySize, smemA);
    cudaFuncSetAttribute(lin_attn_chunk,  cudaFuncAttributeMaxDynamicSharedMemorySize, smemC);

    rmsnorm_kernel<<<ROWS, 256>>>(x, norm_w, h);

    sgemm128<<<dim3(DMODEL / 128, ROWS / 128), 256>>>(h, Wq, q, nullptr, ROWS, DMODEL, DMODEL);
    sgemm128<<<dim3(DMODEL / 128, ROWS / 128), 256>>>(h, Wk, k, nullptr, ROWS, DMODEL, DMODEL);
    sgemm128<<<dim3(DMODEL / 128, ROWS / 128), 256>>>(h, Wv, v, nullptr, ROWS, DMODEL, DMODEL);

    feat_proj<<<HROWS / 16, 256>>>(q, Wqf, qf);
    feat_proj<<<HROWS / 16, 256>>>(k, Wkf, kf);

    taylor_phi<<<HROWS / 256, 256>>>(qf, qphi, HROWS);
    taylor_phi<<<HROWS / 256, 256>>>(kf, kphi, HROWS);

    chunk_kv_kernel<<<BATCH * NH * NCHUNK, 256, smemA>>>(kphi, v, ckv, cks);
    prefix_kv<<<(32 * FDIM * 64 + 255) / 256, 256>>>(ckv, cks);
    lin_attn_chunk<<<BATCH * NH * NCHUNK, 256, smemC>>>(qphi, kphi, v, ckv, cks, cat);

    swa_kernel<<<ROWS * NH, 64>>>(q, k, v, cat);

    sgemm128<<<dim3(DMODEL / 128, ROWS / 128), 256>>>(cat, Wout, out, x, ROWS, DMODEL, 2 * DMODEL);
}

// round 2
// speedup vs baseline: 2.7086x; 2.7086x over previous
#include <cuda_runtime.h>
#include <cstdint>

#define BATCH 2
#define SEQ 2048
#define DMODEL 1024
#define NH 16
#define HD 64
#define FEAT 16
#define FDIM 153           // 1 + 16 + 136
#define NCHUNK 16
#define CHUNKSZ 128
#define ROWS (BATCH*SEQ)          // 4096
#define HROWS (BATCH*SEQ*NH)      // 131072

// ------------------------- scratch (static device memory) -------------------
__device__ float g_h[ROWS*DMODEL];
__device__ float g_q[ROWS*DMODEL];
__device__ float g_k[ROWS*DMODEL];
__device__ float g_v[ROWS*DMODEL];
__device__ float g_qf[HROWS*FEAT];
__device__ float g_kf[HROWS*FEAT];
__device__ float g_qphi[(size_t)HROWS*FDIM];
__device__ float g_kphi[(size_t)HROWS*FDIM];
__device__ float g_ckv[(size_t)BATCH*NH*NCHUNK*FDIM*HD];
__device__ float g_cks[(size_t)BATCH*NH*NCHUNK*FDIM];
__device__ float g_cat[(size_t)ROWS*2*DMODEL];

__device__ __forceinline__ uint32_t f2tf32(float f) {
    uint32_t u;
    asm("cvt.rna.tf32.f32 %0, %1;" : "=r"(u) : "f"(f));
    return u;
}

// ------------------------------- RMSNorm ------------------------------------
__global__ void rmsnorm_kernel(const float* __restrict__ x,
                               const float* __restrict__ w,
                               float* __restrict__ h) {
    int row = blockIdx.x;
    const float* xr = x + (size_t)row * DMODEL;
    float s = 0.f;
    for (int i = threadIdx.x; i < DMODEL; i += 256) { float v = xr[i]; s += v * v; }
    __shared__ float red[8];
    #pragma unroll
    for (int o = 16; o > 0; o >>= 1) s += __shfl_xor_sync(0xffffffffu, s, o);
    if ((threadIdx.x & 31) == 0) red[threadIdx.x >> 5] = s;
    __syncthreads();
    if (threadIdx.x < 8) {
        float v = red[threadIdx.x];
        #pragma unroll
        for (int o = 4; o > 0; o >>= 1) v += __shfl_xor_sync(0xffu, v, o);
        if (threadIdx.x == 0) red[0] = v;
    }
    __syncthreads();
    float rs = rsqrtf(red[0] / (float)DMODEL + 1e-6f);
    float* hr = h + (size_t)row * DMODEL;
    for (int i = threadIdx.x; i < DMODEL; i += 256) hr[i] = xr[i] * rs * w[i];
}

// ------------------------- TF32 tensor-core GEMM -----------------------------
// C[M,N] = A[M,K] @ B[K,N] (+ residual). M%128==0, N%128==0, K%16==0.
// 256 threads, 8 warps in 2x4 grid, warp tile 64x32, mma.m16n8k8.tf32.
__global__ __launch_bounds__(256) void gemm_tf32(
        const float* __restrict__ A, const float* __restrict__ B,
        float* __restrict__ C, const float* __restrict__ residual,
        int M, int N, int K) {
    __shared__ uint32_t As[2][16][136];
    __shared__ uint32_t Bs[2][16][136];
    int tid = threadIdx.x;
    int warp = tid >> 5, lane = tid & 31;
    int wm = (warp >> 2) * 64;
    int wn = (warp & 3) * 32;
    int bm = blockIdx.y * 128, bn = blockIdx.x * 128;
    int r = lane >> 2, cq = lane & 3;

    float acc[4][4][4];
    #pragma unroll
    for (int mi = 0; mi < 4; mi++)
        #pragma unroll
        for (int ni = 0; ni < 4; ni++)
            #pragma unroll
            for (int e = 0; e < 4; e++) acc[mi][ni][e] = 0.f;

    int am = tid >> 2;           // 0..63
    int ak = (tid & 3) * 4;      // 0,4,8,12
    int bk = tid >> 5;           // 0..7
    int bn4 = (tid & 31) * 4;

    const float* Arow0 = A + (size_t)(bm + am) * K + ak;
    const float* Arow1 = A + (size_t)(bm + am + 64) * K + ak;
    const float* Brow0 = B + (size_t)bk * N + bn + bn4;
    const float* Brow1 = B + (size_t)(bk + 8) * N + bn + bn4;

    // preload tile 0
    {
        float4 a0 = *(const float4*)(Arow0);
        float4 a1 = *(const float4*)(Arow1);
        float4 b0 = *(const float4*)(Brow0);
        float4 b1 = *(const float4*)(Brow1);
        As[0][ak+0][am] = f2tf32(a0.x); As[0][ak+1][am] = f2tf32(a0.y);
        As[0][ak+2][am] = f2tf32(a0.z); As[0][ak+3][am] = f2tf32(a0.w);
        As[0][ak+0][am+64] = f2tf32(a1.x); As[0][ak+1][am+64] = f2tf32(a1.y);
        As[0][ak+2][am+64] = f2tf32(a1.z); As[0][ak+3][am+64] = f2tf32(a1.w);
        Bs[0][bk][bn4+0] = f2tf32(b0.x); Bs[0][bk][bn4+1] = f2tf32(b0.y);
        Bs[0][bk][bn4+2] = f2tf32(b0.z); Bs[0][bk][bn4+3] = f2tf32(b0.w);
        Bs[0][bk+8][bn4+0] = f2tf32(b1.x); Bs[0][bk+8][bn4+1] = f2tf32(b1.y);
        Bs[0][bk+8][bn4+2] = f2tf32(b1.z); Bs[0][bk+8][bn4+3] = f2tf32(b1.w);
    }
    __syncthreads();

    int buf = 0;
    for (int k0 = 0; k0 < K; k0 += 16) {
        float4 a0n, a1n, b0n, b1n;
        bool has = (k0 + 16) < K;
        if (has) {
            a0n = *(const float4*)(Arow0 + k0 + 16);
            a1n = *(const float4*)(Arow1 + k0 + 16);
            b0n = *(const float4*)(Brow0 + (size_t)(k0 + 16) * N);
            b1n = *(const float4*)(Brow1 + (size_t)(k0 + 16) * N);
        }
        #pragma unroll
        for (int ks = 0; ks < 16; ks += 8) {
            uint32_t af[4][4], bf[4][2];
            #pragma unroll
            for (int mi = 0; mi < 4; mi++) {
                int m = wm + mi * 16 + r;
                af[mi][0] = As[buf][ks + cq][m];
                af[mi][1] = As[buf][ks + cq][m + 8];
                af[mi][2] = As[buf][ks + cq + 4][m];
                af[mi][3] = As[buf][ks + cq + 4][m + 8];
            }
            #pragma unroll
            for (int ni = 0; ni < 4; ni++) {
                int n = wn + ni * 8 + r;
                bf[ni][0] = Bs[buf][ks + cq][n];
                bf[ni][1] = Bs[buf][ks + cq + 4][n];
            }
            #pragma unroll
            for (int mi = 0; mi < 4; mi++)
                #pragma unroll
                for (int ni = 0; ni < 4; ni++) {
                    asm volatile(
                        "mma.sync.aligned.m16n8k8.row.col.f32.tf32.tf32.f32 "
                        "{%0,%1,%2,%3}, {%4,%5,%6,%7}, {%8,%9}, {%0,%1,%2,%3};"
                        : "+f"(acc[mi][ni][0]), "+f"(acc[mi][ni][1]),
                          "+f"(acc[mi][ni][2]), "+f"(acc[mi][ni][3])
                        : "r"(af[mi][0]), "r"(af[mi][1]), "r"(af[mi][2]), "r"(af[mi][3]),
                          "r"(bf[ni][0]), "r"(bf[ni][1]));
                }
        }
        if (has) {
            int nb = buf ^ 1;
            As[nb][ak+0][am] = f2tf32(a0n.x); As[nb][ak+1][am] = f2tf32(a0n.y);
            As[nb][ak+2][am] = f2tf32(a0n.z); As[nb][ak+3][am] = f2tf32(a0n.w);
            As[nb][ak+0][am+64] = f2tf32(a1n.x); As[nb][ak+1][am+64] = f2tf32(a1n.y);
            As[nb][ak+2][am+64] = f2tf32(a1n.z); As[nb][ak+3][am+64] = f2tf32(a1n.w);
            Bs[nb][bk][bn4+0] = f2tf32(b0n.x); Bs[nb][bk][bn4+1] = f2tf32(b0n.y);
            Bs[nb][bk][bn4+2] = f2tf32(b0n.z); Bs[nb][bk][bn4+3] = f2tf32(b0n.w);
            Bs[nb][bk+8][bn4+0] = f2tf32(b1n.x); Bs[nb][bk+8][bn4+1] = f2tf32(b1n.y);
            Bs[nb][bk+8][bn4+2] = f2tf32(b1n.z); Bs[nb][bk+8][bn4+3] = f2tf32(b1n.w);
        }
        __syncthreads();
        buf ^= 1;
    }

    #pragma unroll
    for (int mi = 0; mi < 4; mi++) {
        int row0 = bm + wm + mi * 16 + r;
        #pragma unroll
        for (int ni = 0; ni < 4; ni++) {
            int col = bn + wn + ni * 8 + 2 * cq;
            float2 lo = make_float2(acc[mi][ni][0], acc[mi][ni][1]);
            float2 hi = make_float2(acc[mi][ni][2], acc[mi][ni][3]);
            if (residual) {
                float2 r0 = *(const float2*)(residual + (size_t)row0 * N + col);
                float2 r1 = *(const float2*)(residual + (size_t)(row0 + 8) * N + col);
                lo.x += r0.x; lo.y += r0.y; hi.x += r1.x; hi.y += r1.y;
            }
            *(float2*)(C + (size_t)row0 * N + col) = lo;
            *(float2*)(C + (size_t)(row0 + 8) * N + col) = hi;
        }
    }
}

// ---------------------- per-head 64 -> 16 projection -------------------------
__global__ void feat_proj(const float* __restrict__ Q, const float* __restrict__ W,
                          float* __restrict__ out) {
    __shared__ float Ws[64 * 16];
    __shared__ float Rs[16][64];
    for (int i = threadIdx.x; i < 64 * 16; i += 256) Ws[i] = W[i];
    int r0 = blockIdx.x * 16;
    for (int i = threadIdx.x; i < 16 * 64; i += 256)
        Rs[i >> 6][i & 63] = Q[(size_t)(r0 + (i >> 6)) * 64 + (i & 63)];
    __syncthreads();
    int lr = threadIdx.x >> 4, c = threadIdx.x & 15;
    float acc = 0.f;
    #pragma unroll
    for (int kk = 0; kk < 64; kk++) acc += Rs[lr][kk] * Ws[kk * 16 + c];
    out[(size_t)(r0 + lr) * 16 + c] = acc;
}

// ----------------------------- Taylor feature map ----------------------------
__global__ void taylor_phi(const float* __restrict__ f, float* __restrict__ phi, int rows) {
    int r = blockIdx.x * blockDim.x + threadIdx.x;
    if (r >= rows) return;
    float x[16];
    const float* fr = f + (size_t)r * 16;
    #pragma unroll
    for (int i = 0; i < 16; i++) x[i] = fr[i];
    float* p = phi + (size_t)r * FDIM;
    p[0] = 1.f;
    #pragma unroll
    for (int i = 0; i < 16; i++) p[1 + i] = x[i];
    const float inv = 0.70710678118654752440f;
    int idx = 17;
    #pragma unroll
    for (int i = 0; i < 16; i++) {
        p[idx++] = 0.5f * x[i] * x[i];
        #pragma unroll
        for (int j = i + 1; j < 16; j++) p[idx++] = inv * x[i] * x[j];
    }
}

// --------------------- pass A: per-chunk KV / Ksum sums ----------------------
__global__ void chunk_kv_kernel(const float* __restrict__ kphi, const float* __restrict__ v,
                                float* __restrict__ ckv, float* __restrict__ cks) {
    int bhc = blockIdx.x;
    int c = bhc & 15; int bh = bhc >> 4;
    int b = bh >> 4, hh = bh & 15;
    extern __shared__ float sm[];
    float* ks_s = sm;                     // 128*153
    float* vs_s = sm + 128 * FDIM;        // 128*64
    size_t tokbase = (size_t)(b * SEQ + c * CHUNKSZ) * NH + hh;
    for (int i = threadIdx.x; i < 128 * FDIM; i += 256) {
        int s = i / FDIM, f = i % FDIM;
        ks_s[i] = kphi[(tokbase + (size_t)s * NH) * FDIM + f];
    }
    for (int i = threadIdx.x; i < 128 * 64; i += 256) {
        int s = i >> 6, d = i & 63;
        vs_s[i] = v[(tokbase + (size_t)s * NH) * HD + d];
    }
    __syncthreads();
    for (int idx = threadIdx.x; idx < FDIM * 64; idx += 256) {
        int f = idx >> 6, d = idx & 63;
        float acc = 0.f;
        for (int s = 0; s < 128; s++) acc += ks_s[s * FDIM + f] * vs_s[s * 64 + d];
        ckv[(size_t)bhc * FDIM * 64 + idx] = acc;
    }
    for (int f = threadIdx.x; f < FDIM; f += 256) {
        float acc = 0.f;
        for (int s = 0; s < 128; s++) acc += ks_s[s * FDIM + f];
        cks[(size_t)bhc * FDIM + f] = acc;
    }
}

// --------------------- pass B: exclusive prefix over chunks ------------------
__global__ void prefix_kv(float* __restrict__ ckv, float* __restrict__ cks) {
    int idx = blockIdx.x * blockDim.x + threadIdx.x;
    const int FD = FDIM * 64;
    if (idx < 32 * FD) {
        int bh = idx / FD, fd = idx % FD;
        float run = 0.f;
        for (int c = 0; c < NCHUNK; c++) {
            size_t o = ((size_t)bh * NCHUNK + c) * FD + fd;
            float cur = ckv[o]; ckv[o] = run; run += cur;
        }
    }
    if (idx < 32 * FDIM) {
        int bh = idx / FDIM, f = idx % FDIM;
        float run = 0.f;
        for (int c = 0; c < NCHUNK; c++) {
            size_t o = ((size_t)bh * NCHUNK + c) * FDIM + f;
            float cur = cks[o]; cks[o] = run; run += cur;
        }
    }
}

// --------------------- pass C: per-chunk linear attention --------------------
__global__ void lin_attn_chunk(const float* __restrict__ qphi, const float* __restrict__ kphi,
                               const float* __restrict__ vv, const float* __restrict__ ckv,
                               const float* __restrict__ cks, float* __restrict__ cat) {
    int bhc = blockIdx.x; int c = bhc & 15; int bh = bhc >> 4;
    int b = bh >> 4, hh = bh & 15;
    extern __shared__ float sm[];
    float* As  = sm;                 // 128*128
    float* Qs  = As + 128 * 128;     // 16*128
    float* Ks  = Qs + 16 * 128;      // 16*128
    float* KVs = Ks + 16 * 128;      // 16*64
    float* KSs = KVs + 16 * 64;      // 16
    float* Vs  = KSs + 16;           // 128*64
    float* Zs  = Vs + 128 * 64;      // 128
    int tid = threadIdx.x; int tx = tid & 15, ty = tid >> 4;
    float acc[8][8], y[8][4], zq[8];
    #pragma unroll
    for (int i = 0; i < 8; i++) {
        zq[i] = 0.f;
        #pragma unroll
        for (int j = 0; j < 8; j++) acc[i][j] = 0.f;
        #pragma unroll
        for (int j = 0; j < 4; j++) y[i][j] = 0.f;
    }
    size_t tokbase = (size_t)(b * SEQ + c * CHUNKSZ) * NH + hh;
    const float* kvb = ckv + (size_t)bhc * FDIM * 64;
    const float* ksb = cks + (size_t)bhc * FDIM;

    for (int f0 = 0; f0 < FDIM; f0 += 16) {
        int ft = min(16, FDIM - f0);
        for (int i = tid; i < 128 * 16; i += 256) {
            int rr = i >> 4, kk = i & 15;
            float a = 0.f, bb = 0.f;
            if (kk < ft) {
                size_t ro = (tokbase + (size_t)rr * NH) * FDIM + f0 + kk;
                a = qphi[ro]; bb = kphi[ro];
            }
            Qs[kk * 128 + rr] = a; Ks[kk * 128 + rr] = bb;
        }
        for (int i = tid; i < 16 * 64; i += 256) {
            int kk = i >> 6, d = i & 63;
            KVs[i] = (kk < ft) ? kvb[(size_t)(f0 + kk) * 64 + d] : 0.f;
        }
        if (tid < 16) KSs[tid] = (tid < ft) ? ksb[f0 + tid] : 0.f;
        __syncthreads();
        for (int kk = 0; kk < ft; kk++) {
            float ar[8], br[8], kvr[4];
            #pragma unroll
            for (int i = 0; i < 8; i++) ar[i] = Qs[kk * 128 + ty * 8 + i];
            #pragma unroll
            for (int j = 0; j < 8; j++) br[j] = Ks[kk * 128 + tx * 8 + j];
            #pragma unroll
            for (int j = 0; j < 4; j++) kvr[j] = KVs[kk * 64 + tx * 4 + j];
            float kss = KSs[kk];
            #pragma unroll
            for (int i = 0; i < 8; i++) {
                #pragma unroll
                for (int j = 0; j < 8; j++) acc[i][j] += ar[i] * br[j];
                #pragma unroll
                for (int j = 0; j < 4; j++) y[i][j] += ar[i] * kvr[j];
                zq[i] += ar[i] * kss;
            }
        }
        __syncthreads();
    }
    #pragma unroll
    for (int i = 0; i < 8; i++) {
        int cr = ty * 8 + i;
        #pragma unroll
        for (int j = 0; j < 8; j++) {
            int s = tx * 8 + j;
            As[cr * 128 + s] = (s <= cr) ? acc[i][j] : 0.f;
        }
    }
    for (int i = tid; i < 128 * 64; i += 256) {
        int s = i >> 6, d = i & 63;
        Vs[i] = vv[(tokbase + (size_t)s * NH) * HD + d];
    }
    __syncthreads();
    if (tx == 0) {
        #pragma unroll
        for (int i = 0; i < 8; i++) {
            int cr = ty * 8 + i;
            float z = zq[i];
            for (int s = 0; s <= cr; s++) z += As[cr * 128 + s];
            Zs[cr] = z + 1e-6f;
        }
    }
    __syncthreads();
    for (int s = 0; s < 128; s++) {
        float av[8], vr[4];
        #pragma unroll
        for (int i = 0; i < 8; i++) av[i] = As[(ty * 8 + i) * 128 + s];
        #pragma unroll
        for (int j = 0; j < 4; j++) vr[j] = Vs[s * 64 + tx * 4 + j];
        #pragma unroll
        for (int i = 0; i < 8; i++)
            #pragma unroll
            for (int j = 0; j < 4; j++) y[i][j] += av[i] * vr[j];
    }
    #pragma unroll
    for (int i = 0; i < 8; i++) {
        int cr = ty * 8 + i;
        float invz = 1.f / Zs[cr];
        size_t row = (size_t)b * SEQ + c * CHUNKSZ + cr;
        #pragma unroll
        for (int j = 0; j < 4; j++)
            cat[row * (2 * DMODEL) + hh * HD + tx * 4 + j] = y[i][j] * invz;
    }
}

// ------------------- sliding-window attention (tiled) ------------------------
// Block: 64 queries x 1 head x 1 batch. Window keys staged once in smem.
__global__ __launch_bounds__(256) void swa_v2(const float* __restrict__ q,
                                              const float* __restrict__ k,
                                              const float* __restrict__ v,
                                              float* __restrict__ cat) {
    int qt = blockIdx.x;        // 0..31 (query tile within seq)
    int hh = blockIdx.y;        // head
    int b  = blockIdx.z;        // batch
    extern __shared__ float sm[];
    float* QsT = sm;                 // [64 e][68]: QsT[e*68 + tok]
    float* KsT = sm + 64 * 68;       // [64 e][132]: KsT[e*132 + c]  (reused as Ps)
    float* Vs  = KsT + 64 * 132;     // [128 s][65]: Vs[s*65 + d]
    float* Ps  = KsT;                // alias: Ps[r*132 + s]

    int tid = threadIdx.x;
    int tx = tid & 15, ty = tid >> 4;
    int q0 = qt * 64;

    for (int i = tid; i < 64 * 64; i += 256) {
        int tok = i >> 6, e = i & 63;
        QsT[e * 68 + tok] = q[((size_t)(b * SEQ + q0 + tok) * DMODEL) + hh * 64 + e];
    }
    for (int i = tid; i < 128 * 64; i += 256) {
        int c = i >> 6, e = i & 63;
        int kg = q0 - 64 + c;
        KsT[e * 132 + c] = (kg >= 0) ? k[((size_t)(b * SEQ + kg) * DMODEL) + hh * 64 + e] : 0.f;
    }
    for (int i = tid; i < 128 * 64; i += 256) {
        int s = i >> 6, d = i & 63;
        int kg = q0 - 64 + s;
        Vs[s * 65 + d] = (kg >= 0) ? v[((size_t)(b * SEQ + kg) * DMODEL) + hh * 64 + d] : 0.f;
    }
    __syncthreads();

    // scores: rows r = 4*ty + i, cols c = tx + 16*j
    float sacc[4][8];
    #pragma unroll
    for (int i = 0; i < 4; i++)
        #pragma unroll
        for (int j = 0; j < 8; j++) sacc[i][j] = 0.f;
    for (int e = 0; e < 64; e++) {
        float qr[4], kr[8];
        #pragma unroll
        for (int i = 0; i < 4; i++) qr[i] = QsT[e * 68 + ty * 4 + i];
        #pragma unroll
        for (int j = 0; j < 8; j++) kr[j] = KsT[e * 132 + tx + 16 * j];
        #pragma unroll
        for (int i = 0; i < 4; i++)
            #pragma unroll
            for (int j = 0; j < 8; j++) sacc[i][j] += qr[i] * kr[j];
    }

    // mask + scale + row max
    float rmax[4];
    #pragma unroll
    for (int i = 0; i < 4; i++) rmax[i] = -1e30f;
    bool edge = (qt == 0);
    #pragma unroll
    for (int i = 0; i < 4; i++) {
        int r = ty * 4 + i;
        #pragma unroll
        for (int j = 0; j < 8; j++) {
            int c = tx + 16 * j;
            bool ok = (c >= r) && (c <= r + 64) && (!edge || c >= 64);
            sacc[i][j] = ok ? sacc[i][j] * 0.125f : -1e30f;
            rmax[i] = fmaxf(rmax[i], sacc[i][j]);
        }
    }
    #pragma unroll
    for (int i = 0; i < 4; i++)
        #pragma unroll
        for (int o = 8; o > 0; o >>= 1)
            rmax[i] = fmaxf(rmax[i], __shfl_xor_sync(0xffffffffu, rmax[i], o));

    float rsum[4];
    #pragma unroll
    for (int i = 0; i < 4; i++) rsum[i] = 0.f;
    #pragma unroll
    for (int i = 0; i < 4; i++)
        #pragma unroll
        for (int j = 0; j < 8; j++) {
            float p = __expf(sacc[i][j] - rmax[i]);
            sacc[i][j] = p;
            rsum[i] += p;
        }
    #pragma unroll
    for (int i = 0; i < 4; i++)
        #pragma unroll
        for (int o = 8; o > 0; o >>= 1)
            rsum[i] += __shfl_xor_sync(0xffffffffu, rsum[i], o);

    __syncthreads();   // everyone done reading KsT
    #pragma unroll
    for (int i = 0; i < 4; i++)
        #pragma unroll
        for (int j = 0; j < 8; j++)
            Ps[(ty * 4 + i) * 132 + tx + 16 * j] = sacc[i][j];
    __syncthreads();

    // O = P @ V : rows r = 4*ty + i, cols d = tx + 16*jj
    float oacc[4][4];
    #pragma unroll
    for (int i = 0; i < 4; i++)
        #pragma unroll
        for (int jj = 0; jj < 4; jj++) oacc[i][jj] = 0.f;
    for (int s = 0; s < 128; s++) {
        float pr[4], vr[4];
        #pragma unroll
        for (int i = 0; i < 4; i++) pr[i] = Ps[(ty * 4 + i) * 132 + s];
        #pragma unroll
        for (int jj = 0; jj < 4; jj++) vr[jj] = Vs[s * 65 + tx + 16 * jj];
        #pragma unroll
        for (int i = 0; i < 4; i++)
            #pragma unroll
            for (int jj = 0; jj < 4; jj++) oacc[i][jj] += pr[i] * vr[jj];
    }
    #pragma unroll
    for (int i = 0; i < 4; i++) {
        float invz = 1.f / rsum[i];
        size_t row = (size_t)(b * SEQ + q0 + ty * 4 + i);
        #pragma unroll
        for (int jj = 0; jj < 4; jj++)
            cat[row * (2 * DMODEL) + DMODEL + hh * 64 + tx + 16 * jj] = oacc[i][jj] * invz;
    }
}

// ---------------------------------- launch -----------------------------------
extern "C" void kernel_launch(void* const* d_in, const int* in_sizes, int n_in,
                              void* d_out, int out_size) {
    const float* x      = (const float*)d_in[0];
    const float* norm_w = (const float*)d_in[1];
    const float* Wq     = (const float*)d_in[2];
    const float* Wk     = (const float*)d_in[3];
    const float* Wv     = (const float*)d_in[4];
    const float* Wqf    = (const float*)d_in[5];
    const float* Wkf    = (const float*)d_in[6];
    const float* Wout   = (const float*)d_in[7];
    float* out = (float*)d_out;

    float *h, *q, *k, *v, *qf, *kf, *qphi, *kphi, *ckv, *cks, *cat;
    cudaGetSymbolAddress((void**)&h,    g_h);
    cudaGetSymbolAddress((void**)&q,    g_q);
    cudaGetSymbolAddress((void**)&k,    g_k);
    cudaGetSymbolAddress((void**)&v,    g_v);
    cudaGetSymbolAddress((void**)&qf,   g_qf);
    cudaGetSymbolAddress((void**)&kf,   g_kf);
    cudaGetSymbolAddress((void**)&qphi, g_qphi);
    cudaGetSymbolAddress((void**)&kphi, g_kphi);
    cudaGetSymbolAddress((void**)&ckv,  g_ckv);
    cudaGetSymbolAddress((void**)&cks,  g_cks);
    cudaGetSymbolAddress((void**)&cat,  g_cat);

    const int smemA = (128 * FDIM + 128 * 64) * 4;                          // 111104
    const int smemC = (128*128 + 16*128*2 + 16*64 + 16 + 128*64 + 128) * 4; // 119360
    const int smemS = (64*68 + 64*132 + 128*65) * 4;                        // 84480
    cudaFuncSetAttribute(chunk_kv_kernel, cudaFuncAttributeMaxDynamicSharedMemorySize, smemA);
    cudaFuncSetAttribute(lin_attn_chunk,  cudaFuncAttributeMaxDynamicSharedMemorySize, smemC);
    cudaFuncSetAttribute(swa_v2,          cudaFuncAttributeMaxDynamicSharedMemorySize, smemS);

    rmsnorm_kernel<<<ROWS, 256>>>(x, norm_w, h);

    gemm_tf32<<<dim3(DMODEL / 128, ROWS / 128), 256>>>(h, Wq, q, nullptr, ROWS, DMODEL, DMODEL);
    gemm_tf32<<<dim3(DMODEL / 128, ROWS / 128), 256>>>(h, Wk, k, nullptr, ROWS, DMODEL, DMODEL);
    gemm_tf32<<<dim3(DMODEL / 128, ROWS / 128), 256>>>(h, Wv, v, nullptr, ROWS, DMODEL, DMODEL);

    feat_proj<<<HROWS / 16, 256>>>(q, Wqf, qf);
    feat_proj<<<HROWS / 16, 256>>>(k, Wkf, kf);

    taylor_phi<<<HROWS / 256, 256>>>(qf, qphi, HROWS);
    taylor_phi<<<HROWS / 256, 256>>>(kf, kphi, HROWS);

    chunk_kv_kernel<<<BATCH * NH * NCHUNK, 256, smemA>>>(kphi, v, ckv, cks);
    prefix_kv<<<(32 * FDIM * 64 + 255) / 256, 256>>>(ckv, cks);
    lin_attn_chunk<<<BATCH * NH * NCHUNK, 256, smemC>>>(qphi, kphi, v, ckv, cks, cat);

    swa_v2<<<dim3(SEQ / 64, NH, BATCH), 256, smemS>>>(q, k, v, cat);

    gemm_tf32<<<dim3(DMODEL / 128, ROWS / 128), 256>>>(cat, Wout, out, x, ROWS, DMODEL, 2 * DMODEL);
}

// round 3
// speedup vs baseline: 3.6489x; 1.3471x over previous
#include <cuda_runtime.h>
#include <cstdint>

#define BATCH 2
#define SEQ 2048
#define DMODEL 1024
#define NH 16
#define HD 64
#define FEAT 16
#define FDIM 153           // 1 + 16 + 136
#define FPAD 160           // padded feature dim (mult of 8, zero-filled tail)
#define NCHUNK 16
#define CHUNKSZ 128
#define ROWS (BATCH*SEQ)          // 4096
#define HROWS (BATCH*SEQ*NH)      // 131072

// ------------------------- scratch (static device memory) -------------------
__device__ float g_h[ROWS*DMODEL];
__device__ float g_q[ROWS*DMODEL];
__device__ float g_k[ROWS*DMODEL];
__device__ float g_v[ROWS*DMODEL];
__device__ float g_qf[HROWS*FEAT];
__device__ float g_kf[HROWS*FEAT];
__device__ float g_qphi[(size_t)HROWS*FPAD];
__device__ float g_kphi[(size_t)HROWS*FPAD];
__device__ float g_ckv[(size_t)BATCH*NH*NCHUNK*FPAD*72];   // [bhc][160][72] (col64 = ksum)
__device__ float g_cat[(size_t)ROWS*2*DMODEL];

__device__ __forceinline__ uint32_t f2tf32(float f) {
    uint32_t u;
    asm("cvt.rna.tf32.f32 %0, %1;" : "=r"(u) : "f"(f));
    return u;
}

__device__ __forceinline__ void mma8(float acc[4], uint32_t a0, uint32_t a1,
                                     uint32_t a2, uint32_t a3,
                                     uint32_t b0, uint32_t b1) {
    asm volatile(
        "mma.sync.aligned.m16n8k8.row.col.f32.tf32.tf32.f32 "
        "{%0,%1,%2,%3}, {%4,%5,%6,%7}, {%8,%9}, {%0,%1,%2,%3};"
        : "+f"(acc[0]), "+f"(acc[1]), "+f"(acc[2]), "+f"(acc[3])
        : "r"(a0), "r"(a1), "r"(a2), "r"(a3), "r"(b0), "r"(b1));
}

// ------------------------------- RMSNorm ------------------------------------
__global__ void rmsnorm_kernel(const float* __restrict__ x,
                               const float* __restrict__ w,
                               float* __restrict__ h) {
    int row = blockIdx.x;
    const float* xr = x + (size_t)row * DMODEL;
    float s = 0.f;
    for (int i = threadIdx.x; i < DMODEL; i += 256) { float v = xr[i]; s += v * v; }
    __shared__ float red[8];
    #pragma unroll
    for (int o = 16; o > 0; o >>= 1) s += __shfl_xor_sync(0xffffffffu, s, o);
    if ((threadIdx.x & 31) == 0) red[threadIdx.x >> 5] = s;
    __syncthreads();
    if (threadIdx.x < 8) {
        float v = red[threadIdx.x];
        #pragma unroll
        for (int o = 4; o > 0; o >>= 1) v += __shfl_xor_sync(0xffu, v, o);
        if (threadIdx.x == 0) red[0] = v;
    }
    __syncthreads();
    float rs = rsqrtf(red[0] / (float)DMODEL + 1e-6f);
    float* hr = h + (size_t)row * DMODEL;
    for (int i = threadIdx.x; i < DMODEL; i += 256) hr[i] = xr[i] * rs * w[i];
}

// ------------------------- TF32 tensor-core GEMM -----------------------------
__global__ __launch_bounds__(256) void gemm_tf32(
        const float* __restrict__ A, const float* __restrict__ B,
        float* __restrict__ C, const float* __restrict__ residual,
        int M, int N, int K) {
    __shared__ uint32_t As[2][16][136];
    __shared__ uint32_t Bs[2][16][136];
    int tid = threadIdx.x;
    int warp = tid >> 5, lane = tid & 31;
    int wm = (warp >> 2) * 64;
    int wn = (warp & 3) * 32;
    int bm = blockIdx.y * 128, bn = blockIdx.x * 128;
    int r = lane >> 2, cq = lane & 3;

    float acc[4][4][4];
    #pragma unroll
    for (int mi = 0; mi < 4; mi++)
        #pragma unroll
        for (int ni = 0; ni < 4; ni++)
            #pragma unroll
            for (int e = 0; e < 4; e++) acc[mi][ni][e] = 0.f;

    int am = tid >> 2;
    int ak = (tid & 3) * 4;
    int bk = tid >> 5;
    int bn4 = (tid & 31) * 4;

    const float* Arow0 = A + (size_t)(bm + am) * K + ak;
    const float* Arow1 = A + (size_t)(bm + am + 64) * K + ak;
    const float* Brow0 = B + (size_t)bk * N + bn + bn4;
    const float* Brow1 = B + (size_t)(bk + 8) * N + bn + bn4;

    {
        float4 a0 = *(const float4*)(Arow0);
        float4 a1 = *(const float4*)(Arow1);
        float4 b0 = *(const float4*)(Brow0);
        float4 b1 = *(const float4*)(Brow1);
        As[0][ak+0][am] = f2tf32(a0.x); As[0][ak+1][am] = f2tf32(a0.y);
        As[0][ak+2][am] = f2tf32(a0.z); As[0][ak+3][am] = f2tf32(a0.w);
        As[0][ak+0][am+64] = f2tf32(a1.x); As[0][ak+1][am+64] = f2tf32(a1.y);
        As[0][ak+2][am+64] = f2tf32(a1.z); As[0][ak+3][am+64] = f2tf32(a1.w);
        Bs[0][bk][bn4+0] = f2tf32(b0.x); Bs[0][bk][bn4+1] = f2tf32(b0.y);
        Bs[0][bk][bn4+2] = f2tf32(b0.z); Bs[0][bk][bn4+3] = f2tf32(b0.w);
        Bs[0][bk+8][bn4+0] = f2tf32(b1.x); Bs[0][bk+8][bn4+1] = f2tf32(b1.y);
        Bs[0][bk+8][bn4+2] = f2tf32(b1.z); Bs[0][bk+8][bn4+3] = f2tf32(b1.w);
    }
    __syncthreads();

    int buf = 0;
    for (int k0 = 0; k0 < K; k0 += 16) {
        float4 a0n, a1n, b0n, b1n;
        bool has = (k0 + 16) < K;
        if (has) {
            a0n = *(const float4*)(Arow0 + k0 + 16);
            a1n = *(const float4*)(Arow1 + k0 + 16);
            b0n = *(const float4*)(Brow0 + (size_t)(k0 + 16) * N);
            b1n = *(const float4*)(Brow1 + (size_t)(k0 + 16) * N);
        }
        #pragma unroll
        for (int ks = 0; ks < 16; ks += 8) {
            uint32_t af[4][4], bf[4][2];
            #pragma unroll
            for (int mi = 0; mi < 4; mi++) {
                int m = wm + mi * 16 + r;
                af[mi][0] = As[buf][ks + cq][m];
                af[mi][1] = As[buf][ks + cq][m + 8];
                af[mi][2] = As[buf][ks + cq + 4][m];
                af[mi][3] = As[buf][ks + cq + 4][m + 8];
            }
            #pragma unroll
            for (int ni = 0; ni < 4; ni++) {
                int n = wn + ni * 8 + r;
                bf[ni][0] = Bs[buf][ks + cq][n];
                bf[ni][1] = Bs[buf][ks + cq + 4][n];
            }
            #pragma unroll
            for (int mi = 0; mi < 4; mi++)
                #pragma unroll
                for (int ni = 0; ni < 4; ni++)
                    mma8(acc[mi][ni], af[mi][0], af[mi][1], af[mi][2], af[mi][3],
                         bf[ni][0], bf[ni][1]);
        }
        if (has) {
            int nb = buf ^ 1;
            As[nb][ak+0][am] = f2tf32(a0n.x); As[nb][ak+1][am] = f2tf32(a0n.y);
            As[nb][ak+2][am] = f2tf32(a0n.z); As[nb][ak+3][am] = f2tf32(a0n.w);
            As[nb][ak+0][am+64] = f2tf32(a1n.x); As[nb][ak+1][am+64] = f2tf32(a1n.y);
            As[nb][ak+2][am+64] = f2tf32(a1n.z); As[nb][ak+3][am+64] = f2tf32(a1n.w);
            Bs[nb][bk][bn4+0] = f2tf32(b0n.x); Bs[nb][bk][bn4+1] = f2tf32(b0n.y);
            Bs[nb][bk][bn4+2] = f2tf32(b0n.z); Bs[nb][bk][bn4+3] = f2tf32(b0n.w);
            Bs[nb][bk+8][bn4+0] = f2tf32(b1n.x); Bs[nb][bk+8][bn4+1] = f2tf32(b1n.y);
            Bs[nb][bk+8][bn4+2] = f2tf32(b1n.z); Bs[nb][bk+8][bn4+3] = f2tf32(b1n.w);
        }
        __syncthreads();
        buf ^= 1;
    }

    #pragma unroll
    for (int mi = 0; mi < 4; mi++) {
        int row0 = bm + wm + mi * 16 + r;
        #pragma unroll
        for (int ni = 0; ni < 4; ni++) {
            int col = bn + wn + ni * 8 + 2 * cq;
            float2 lo = make_float2(acc[mi][ni][0], acc[mi][ni][1]);
            float2 hi = make_float2(acc[mi][ni][2], acc[mi][ni][3]);
            if (residual) {
                float2 r0 = *(const float2*)(residual + (size_t)row0 * N + col);
                float2 r1 = *(const float2*)(residual + (size_t)(row0 + 8) * N + col);
                lo.x += r0.x; lo.y += r0.y; hi.x += r1.x; hi.y += r1.y;
            }
            *(float2*)(C + (size_t)row0 * N + col) = lo;
            *(float2*)(C + (size_t)(row0 + 8) * N + col) = hi;
        }
    }
}

// ---------------------- per-head 64 -> 16 projection -------------------------
__global__ void feat_proj(const float* __restrict__ Q, const float* __restrict__ W,
                          float* __restrict__ out) {
    __shared__ float Ws[64 * 16];
    __shared__ float Rs[16][64];
    for (int i = threadIdx.x; i < 64 * 16; i += 256) Ws[i] = W[i];
    int r0 = blockIdx.x * 16;
    for (int i = threadIdx.x; i < 16 * 64; i += 256)
        Rs[i >> 6][i & 63] = Q[(size_t)(r0 + (i >> 6)) * 64 + (i & 63)];
    __syncthreads();
    int lr = threadIdx.x >> 4, c = threadIdx.x & 15;
    float acc = 0.f;
    #pragma unroll
    for (int kk = 0; kk < 64; kk++) acc += Rs[lr][kk] * Ws[kk * 16 + c];
    out[(size_t)(r0 + lr) * 16 + c] = acc;
}

// ----------------------------- Taylor feature map ----------------------------
__global__ void taylor_phi(const float* __restrict__ f, float* __restrict__ phi, int rows) {
    int r = blockIdx.x * blockDim.x + threadIdx.x;
    if (r >= rows) return;
    float x[16];
    const float* fr = f + (size_t)r * 16;
    #pragma unroll
    for (int i = 0; i < 16; i++) x[i] = fr[i];
    float* p = phi + (size_t)r * FPAD;
    p[0] = 1.f;
    #pragma unroll
    for (int i = 0; i < 16; i++) p[1 + i] = x[i];
    const float inv = 0.70710678118654752440f;
    int idx = 17;
    #pragma unroll
    for (int i = 0; i < 16; i++) {
        p[idx++] = 0.5f * x[i] * x[i];
        #pragma unroll
        for (int j = i + 1; j < 16; j++) p[idx++] = inv * x[i] * x[j];
    }
    #pragma unroll
    for (int i = FDIM; i < FPAD; i++) p[i] = 0.f;
}

// --------------- pass A: per-chunk KV' = Kphi^T @ [V | 1] (tf32) --------------
// Output ckv[bhc][160][72], col 64 = ksum, cols 65..71 = 0.
__global__ __launch_bounds__(320) void chunk_kv_v2(const float* __restrict__ kphi,
        const float* __restrict__ vv, float* __restrict__ ckv) {
    extern __shared__ uint32_t su[];
    uint32_t* Ks = su;              // [tok 128][feat 164]
    uint32_t* Vs = su + 128 * 164;  // [tok 128][88]
    int tid = threadIdx.x, warp = tid >> 5, lane = tid & 31;
    int r = lane >> 2, cq = lane & 3;
    int bhc = blockIdx.x, c = bhc & 15, bh = bhc >> 4, b = bh >> 4, hh = bh & 15;
    size_t phirow = (size_t)(b * SEQ + c * CHUNKSZ) * NH + hh;
    for (int i = tid; i < 128 * 40; i += 320) {
        int tok = i / 40, qd = (i % 40) * 4;
        float4 t = *(const float4*)(kphi + (phirow + (size_t)tok * NH) * FPAD + qd);
        uint4 u = make_uint4(f2tf32(t.x), f2tf32(t.y), f2tf32(t.z), f2tf32(t.w));
        *(uint4*)(Ks + tok * 164 + qd) = u;
    }
    size_t vrow0 = (size_t)(b * SEQ + c * CHUNKSZ) * DMODEL + hh * HD;
    for (int i = tid; i < 128 * 18; i += 320) {
        int tok = i / 18, qd = (i % 18) * 4;
        uint4 u = make_uint4(0u, 0u, 0u, 0u);
        if (qd < 64) {
            float4 t = *(const float4*)(vv + vrow0 + (size_t)tok * DMODEL + qd);
            u = make_uint4(f2tf32(t.x), f2tf32(t.y), f2tf32(t.z), f2tf32(t.w));
        } else if (qd == 64) u.x = 0x3f800000u;
        *(uint4*)(Vs + tok * 88 + qd) = u;
    }
    __syncthreads();
    float acc[9][4];
    #pragma unroll
    for (int ni = 0; ni < 9; ni++)
        #pragma unroll
        for (int e = 0; e < 4; e++) acc[ni][e] = 0.f;
    int m0 = warp * 16;   // feature rows (M=160, 10 warps)
    for (int kk = 0; kk < 128; kk += 8) {
        uint32_t a0 = Ks[(kk + cq) * 164 + m0 + r];
        uint32_t a1 = Ks[(kk + cq) * 164 + m0 + r + 8];
        uint32_t a2 = Ks[(kk + cq + 4) * 164 + m0 + r];
        uint32_t a3 = Ks[(kk + cq + 4) * 164 + m0 + r + 8];
        #pragma unroll
        for (int ni = 0; ni < 9; ni++) {
            uint32_t b0 = Vs[(kk + cq) * 88 + ni * 8 + r];
            uint32_t b1 = Vs[(kk + cq + 4) * 88 + ni * 8 + r];
            mma8(acc[ni], a0, a1, a2, a3, b0, b1);
        }
    }
    float* outb = ckv + (size_t)bhc * FPAD * 72;
    #pragma unroll
    for (int ni = 0; ni < 9; ni++) {
        int n = ni * 8 + 2 * cq;
        *(float2*)(outb + (m0 + r) * 72 + n)     = make_float2(acc[ni][0], acc[ni][1]);
        *(float2*)(outb + (m0 + r + 8) * 72 + n) = make_float2(acc[ni][2], acc[ni][3]);
    }
}

// --------------------- pass B: exclusive prefix over chunks ------------------
__global__ void prefix_kv_v2(float* __restrict__ ckv) {
    const int FD = FPAD * 72;
    int idx = blockIdx.x * 256 + threadIdx.x;
    if (idx >= 32 * FD) return;
    int bh = idx / FD, e = idx % FD;
    size_t base = (size_t)bh * NCHUNK * FD + e;
    float run = 0.f;
    for (int c = 0; c < NCHUNK; c++) {
        float cur = ckv[base + (size_t)c * FD];
        ckv[base + (size_t)c * FD] = run;
        run += cur;
    }
}

// --------------- pass C: per-chunk linear attention (tf32 mma) ----------------
__global__ __launch_bounds__(256) void lin_attn_v3(const float* __restrict__ qphi,
        const float* __restrict__ kphi, const float* __restrict__ vv,
        const float* __restrict__ ckv, float* __restrict__ cat) {
    extern __shared__ uint32_t su[];
    uint32_t* Qs  = su;                    // [k 160][m 132]
    uint32_t* Ks  = su + 160 * 132;        // [k 160][n 132]
    uint32_t* KVs = Ks + 160 * 132;        // [k 160][n 88]
    uint32_t* Am  = Ks;                    // overlay: [k 128][m 132]
    uint32_t* Vs  = Ks + 128 * 132;        // overlay: [k 128][n 88]
    int tid = threadIdx.x, warp = tid >> 5, lane = tid & 31;
    int r = lane >> 2, cq = lane & 3;
    int bhc = blockIdx.x, c = bhc & 15, bh = bhc >> 4, b = bh >> 4, hh = bh & 15;
    size_t phirow = (size_t)(b * SEQ + c * CHUNKSZ) * NH + hh;

    for (int i = tid; i < 128 * 40; i += 256) {
        int tok = i / 40, qd = (i % 40) * 4;
        float4 qv = *(const float4*)(qphi + (phirow + (size_t)tok * NH) * FPAD + qd);
        float4 kv = *(const float4*)(kphi + (phirow + (size_t)tok * NH) * FPAD + qd);
        Qs[(qd + 0) * 132 + tok] = f2tf32(qv.x);
        Qs[(qd + 1) * 132 + tok] = f2tf32(qv.y);
        Qs[(qd + 2) * 132 + tok] = f2tf32(qv.z);
        Qs[(qd + 3) * 132 + tok] = f2tf32(qv.w);
        Ks[(qd + 0) * 132 + tok] = f2tf32(kv.x);
        Ks[(qd + 1) * 132 + tok] = f2tf32(kv.y);
        Ks[(qd + 2) * 132 + tok] = f2tf32(kv.z);
        Ks[(qd + 3) * 132 + tok] = f2tf32(kv.w);
    }
    const float* kvb = ckv + (size_t)bhc * FPAD * 72;
    for (int i = tid; i < 160 * 36; i += 256) {
        int f = i / 36, n = (i % 36) * 2;
        float2 t = *(const float2*)(kvb + f * 72 + n);
        KVs[f * 88 + n]     = f2tf32(t.x);
        KVs[f * 88 + n + 1] = f2tf32(t.y);
    }
    __syncthreads();

    // GEMM2: Y1z = Qphi @ KV'   (M=128 rows, warp w owns rows 16w..16w+15)
    float accy[9][4];
    #pragma unroll
    for (int ni = 0; ni < 9; ni++)
        #pragma unroll
        for (int e = 0; e < 4; e++) accy[ni][e] = 0.f;
    int m0 = warp * 16;
    for (int kk = 0; kk < 160; kk += 8) {
        uint32_t a0 = Qs[(kk + cq) * 132 + m0 + r];
        uint32_t a1 = Qs[(kk + cq) * 132 + m0 + r + 8];
        uint32_t a2 = Qs[(kk + cq + 4) * 132 + m0 + r];
        uint32_t a3 = Qs[(kk + cq + 4) * 132 + m0 + r + 8];
        #pragma unroll
        for (int ni = 0; ni < 9; ni++) {
            uint32_t b0 = KVs[(kk + cq) * 88 + ni * 8 + r];
            uint32_t b1 = KVs[(kk + cq + 4) * 88 + ni * 8 + r];
            mma8(accy[ni], a0, a1, a2, a3, b0, b1);
        }
    }

    // GEMM1: S = Qphi @ Kphi^T (128x128), warp tile 64x32
    float acc1[4][4][4];
    #pragma unroll
    for (int mi = 0; mi < 4; mi++)
        #pragma unroll
        for (int ni = 0; ni < 4; ni++)
            #pragma unroll
            for (int e = 0; e < 4; e++) acc1[mi][ni][e] = 0.f;
    int wm = (warp >> 2) * 64, wn = (warp & 3) * 32;
    for (int kk = 0; kk < 160; kk += 8) {
        uint32_t af[4][4];
        #pragma unroll
        for (int mi = 0; mi < 4; mi++) {
            int m = wm + mi * 16;
            af[mi][0] = Qs[(kk + cq) * 132 + m + r];
            af[mi][1] = Qs[(kk + cq) * 132 + m + r + 8];
            af[mi][2] = Qs[(kk + cq + 4) * 132 + m + r];
            af[mi][3] = Qs[(kk + cq + 4) * 132 + m + r + 8];
        }
        #pragma unroll
        for (int ni = 0; ni < 4; ni++) {
            uint32_t b0 = Ks[(kk + cq) * 132 + wn + ni * 8 + r];
            uint32_t b1 = Ks[(kk + cq + 4) * 132 + wn + ni * 8 + r];
            #pragma unroll
            for (int mi = 0; mi < 4; mi++)
                mma8(acc1[mi][ni], af[mi][0], af[mi][1], af[mi][2], af[mi][3], b0, b1);
        }
    }
    __syncthreads();

    // store masked A transposed ([k=s][m=row]) as tf32, load V'
    #pragma unroll
    for (int mi = 0; mi < 4; mi++) {
        int row = wm + mi * 16 + r;
        #pragma unroll
        for (int ni = 0; ni < 4; ni++) {
            int col = wn + ni * 8 + 2 * cq;
            Am[col * 132 + row]           = (col     <= row)     ? f2tf32(acc1[mi][ni][0]) : 0u;
            Am[(col + 1) * 132 + row]     = (col + 1 <= row)     ? f2tf32(acc1[mi][ni][1]) : 0u;
            Am[col * 132 + row + 8]       = (col     <= row + 8) ? f2tf32(acc1[mi][ni][2]) : 0u;
            Am[(col + 1) * 132 + row + 8] = (col + 1 <= row + 8) ? f2tf32(acc1[mi][ni][3]) : 0u;
        }
    }
    size_t vrow0 = (size_t)(b * SEQ + c * CHUNKSZ) * DMODEL + hh * HD;
    for (int i = tid; i < 128 * 18; i += 256) {
        int tok = i / 18, qd = (i % 18) * 4;
        uint4 u = make_uint4(0u, 0u, 0u, 0u);
        if (qd < 64) {
            float4 t = *(const float4*)(vv + vrow0 + (size_t)tok * DMODEL + qd);
            u = make_uint4(f2tf32(t.x), f2tf32(t.y), f2tf32(t.z), f2tf32(t.w));
        } else if (qd == 64) u.x = 0x3f800000u;
        *(uint4*)(Vs + tok * 88 + qd) = u;
    }
    __syncthreads();

    // GEMM3: accy += A @ V'
    for (int kk = 0; kk < 128; kk += 8) {
        uint32_t a0 = Am[(kk + cq) * 132 + m0 + r];
        uint32_t a1 = Am[(kk + cq) * 132 + m0 + r + 8];
        uint32_t a2 = Am[(kk + cq + 4) * 132 + m0 + r];
        uint32_t a3 = Am[(kk + cq + 4) * 132 + m0 + r + 8];
        #pragma unroll
        for (int ni = 0; ni < 9; ni++) {
            uint32_t b0 = Vs[(kk + cq) * 88 + ni * 8 + r];
            uint32_t b1 = Vs[(kk + cq + 4) * 88 + ni * 8 + r];
            mma8(accy[ni], a0, a1, a2, a3, b0, b1);
        }
    }

    float zlo = __shfl_sync(0xffffffffu, accy[8][0], lane & 28) + 1e-6f;
    float zhi = __shfl_sync(0xffffffffu, accy[8][2], lane & 28) + 1e-6f;
    float izlo = 1.f / zlo, izhi = 1.f / zhi;
    size_t rowg = (size_t)(b * SEQ + c * CHUNKSZ + m0 + r);
    #pragma unroll
    for (int ni = 0; ni < 8; ni++) {
        int colg = hh * HD + ni * 8 + 2 * cq;
        *(float2*)(cat + rowg * (2 * DMODEL) + colg) =
            make_float2(accy[ni][0] * izlo, accy[ni][1] * izlo);
        *(float2*)(cat + (rowg + 8) * (2 * DMODEL) + colg) =
            make_float2(accy[ni][2] * izhi, accy[ni][3] * izhi);
    }
}

// ------------------- sliding-window attention (tf32 mma) ---------------------
__global__ __launch_bounds__(128) void swa_v3(const float* __restrict__ q,
        const float* __restrict__ k, const float* __restrict__ v,
        float* __restrict__ cat) {
    extern __shared__ uint32_t su[];
    uint32_t* Qs = su;               // [e 64][tok 68]
    uint32_t* Ks = Qs + 64 * 68;     // [e 64][key 132]
    uint32_t* Ps = Ks + 64 * 132;    // [key 128][tok 68]
    uint32_t* Vs = Ps + 128 * 68;    // [key 128][d 68]
    int tid = threadIdx.x, warp = tid >> 5, lane = tid & 31;
    int r = lane >> 2, cq = lane & 3;
    int q0 = blockIdx.x * 64, hh = blockIdx.y, b = blockIdx.z;

    for (int i = tid; i < 64 * 16; i += 128) {
        int tok = i >> 4, qd = (i & 15) * 4;
        float4 t = *(const float4*)(q + (size_t)(b * SEQ + q0 + tok) * DMODEL + hh * HD + qd);
        Qs[(qd + 0) * 68 + tok] = f2tf32(t.x);
        Qs[(qd + 1) * 68 + tok] = f2tf32(t.y);
        Qs[(qd + 2) * 68 + tok] = f2tf32(t.z);
        Qs[(qd + 3) * 68 + tok] = f2tf32(t.w);
    }
    for (int i = tid; i < 128 * 16; i += 128) {
        int key = i >> 4, qd = (i & 15) * 4;
        int kg = q0 - 64 + key;
        float4 tk = make_float4(0.f, 0.f, 0.f, 0.f);
        float4 tv = make_float4(0.f, 0.f, 0.f, 0.f);
        if (kg >= 0) {
            tk = *(const float4*)(k + (size_t)(b * SEQ + kg) * DMODEL + hh * HD + qd);
            tv = *(const float4*)(v + (size_t)(b * SEQ + kg) * DMODEL + hh * HD + qd);
        }
        Ks[(qd + 0) * 132 + key] = f2tf32(tk.x);
        Ks[(qd + 1) * 132 + key] = f2tf32(tk.y);
        Ks[(qd + 2) * 132 + key] = f2tf32(tk.z);
        Ks[(qd + 3) * 132 + key] = f2tf32(tk.w);
        *(uint4*)(Vs + key * 68 + qd) =
            make_uint4(f2tf32(tv.x), f2tf32(tv.y), f2tf32(tv.z), f2tf32(tv.w));
    }
    __syncthreads();

    // S = Q @ K^T : warp owns rows 16w..16w+15, 16 n-tiles
    float acc[16][4];
    #pragma unroll
    for (int ni = 0; ni < 16; ni++)
        #pragma unroll
        for (int e = 0; e < 4; e++) acc[ni][e] = 0.f;
    int m0 = warp * 16;
    for (int kk = 0; kk < 64; kk += 8) {
        uint32_t a0 = Qs[(kk + cq) * 68 + m0 + r];
        uint32_t a1 = Qs[(kk + cq) * 68 + m0 + r + 8];
        uint32_t a2 = Qs[(kk + cq + 4) * 68 + m0 + r];
        uint32_t a3 = Qs[(kk + cq + 4) * 68 + m0 + r + 8];
        #pragma unroll
        for (int ni = 0; ni < 16; ni++) {
            uint32_t b0 = Ks[(kk + cq) * 132 + ni * 8 + r];
            uint32_t b1 = Ks[(kk + cq + 4) * 132 + ni * 8 + r];
            mma8(acc[ni], a0, a1, a2, a3, b0, b1);
        }
    }

    int rowlo = m0 + r, rowhi = rowlo + 8;
    float mlo = -1e30f, mhi = -1e30f;
    #pragma unroll
    for (int ni = 0; ni < 16; ni++) {
        int n = ni * 8 + 2 * cq;
        bool ok0l = (n     >= rowlo) && (n     <= rowlo + 64) && (q0 - 64 + n     >= 0);
        bool ok1l = (n + 1 >= rowlo) && (n + 1 <= rowlo + 64) && (q0 - 64 + n + 1 >= 0);
        bool ok0h = (n     >= rowhi) && (n     <= rowhi + 64) && (q0 - 64 + n     >= 0);
        bool ok1h = (n + 1 >= rowhi) && (n + 1 <= rowhi + 64) && (q0 - 64 + n + 1 >= 0);
        acc[ni][0] = ok0l ? acc[ni][0] * 0.125f : -1e30f;
        acc[ni][1] = ok1l ? acc[ni][1] * 0.125f : -1e30f;
        acc[ni][2] = ok0h ? acc[ni][2] * 0.125f : -1e30f;
        acc[ni][3] = ok1h ? acc[ni][3] * 0.125f : -1e30f;
        mlo = fmaxf(mlo, fmaxf(acc[ni][0], acc[ni][1]));
        mhi = fmaxf(mhi, fmaxf(acc[ni][2], acc[ni][3]));
    }
    mlo = fmaxf(mlo, __shfl_xor_sync(0xffffffffu, mlo, 1));
    mlo = fmaxf(mlo, __shfl_xor_sync(0xffffffffu, mlo, 2));
    mhi = fmaxf(mhi, __shfl_xor_sync(0xffffffffu, mhi, 1));
    mhi = fmaxf(mhi, __shfl_xor_sync(0xffffffffu, mhi, 2));

    float slo = 0.f, shi = 0.f;
    #pragma unroll
    for (int ni = 0; ni < 16; ni++) {
        acc[ni][0] = __expf(acc[ni][0] - mlo);
        acc[ni][1] = __expf(acc[ni][1] - mlo);
        acc[ni][2] = __expf(acc[ni][2] - mhi);
        acc[ni][3] = __expf(acc[ni][3] - mhi);
        slo += acc[ni][0] + acc[ni][1];
        shi += acc[ni][2] + acc[ni][3];
    }
    slo += __shfl_xor_sync(0xffffffffu, slo, 1);
    slo += __shfl_xor_sync(0xffffffffu, slo, 2);
    shi += __shfl_xor_sync(0xffffffffu, shi, 1);
    shi += __shfl_xor_sync(0xffffffffu, shi, 2);

    #pragma unroll
    for (int ni = 0; ni < 16; ni++) {
        int n = ni * 8 + 2 * cq;
        Ps[n * 68 + rowlo]       = f2tf32(acc[ni][0]);
        Ps[(n + 1) * 68 + rowlo] = f2tf32(acc[ni][1]);
        Ps[n * 68 + rowhi]       = f2tf32(acc[ni][2]);
        Ps[(n + 1) * 68 + rowhi] = f2tf32(acc[ni][3]);
    }
    __syncwarp();

    // O = P @ V
    float accO[8][4];
    #pragma unroll
    for (int ni = 0; ni < 8; ni++)
        #pragma unroll
        for (int e = 0; e < 4; e++) accO[ni][e] = 0.f;
    for (int kk = 0; kk < 128; kk += 8) {
        uint32_t a0 = Ps[(kk + cq) * 68 + m0 + r];
        uint32_t a1 = Ps[(kk + cq) * 68 + m0 + r + 8];
        uint32_t a2 = Ps[(kk + cq + 4) * 68 + m0 + r];
        uint32_t a3 = Ps[(kk + cq + 4) * 68 + m0 + r + 8];
        #pragma unroll
        for (int ni = 0; ni < 8; ni++) {
            uint32_t b0 = Vs[(kk + cq) * 68 + ni * 8 + r];
            uint32_t b1 = Vs[(kk + cq + 4) * 68 + ni * 8 + r];
            mma8(accO[ni], a0, a1, a2, a3, b0, b1);
        }
    }
    float izlo = 1.f / slo, izhi = 1.f / shi;
    #pragma unroll
    for (int ni = 0; ni < 8; ni++) {
        int colg = DMODEL + hh * HD + ni * 8 + 2 * cq;
        *(float2*)(cat + (size_t)(b * SEQ + q0 + rowlo) * (2 * DMODEL) + colg) =
            make_float2(accO[ni][0] * izlo, accO[ni][1] * izlo);
        *(float2*)(cat + (size_t)(b * SEQ + q0 + rowhi) * (2 * DMODEL) + colg) =
            make_float2(accO[ni][2] * izhi, accO[ni][3] * izhi);
    }
}

// ---------------------------------- launch -----------------------------------
extern "C" void kernel_launch(void* const* d_in, const int* in_sizes, int n_in,
                              void* d_out, int out_size) {
    const float* x      = (const float*)d_in[0];
    const float* norm_w = (const float*)d_in[1];
    const float* Wq     = (const float*)d_in[2];
    const float* Wk     = (const float*)d_in[3];
    const float* Wv     = (const float*)d_in[4];
    const float* Wqf    = (const float*)d_in[5];
    const float* Wkf    = (const float*)d_in[6];
    const float* Wout   = (const float*)d_in[7];
    float* out = (float*)d_out;

    float *h, *q, *k, *v, *qf, *kf, *qphi, *kphi, *ckv, *cat;
    cudaGetSymbolAddress((void**)&h,    g_h);
    cudaGetSymbolAddress((void**)&q,    g_q);
    cudaGetSymbolAddress((void**)&k,    g_k);
    cudaGetSymbolAddress((void**)&v,    g_v);
    cudaGetSymbolAddress((void**)&qf,   g_qf);
    cudaGetSymbolAddress((void**)&kf,   g_kf);
    cudaGetSymbolAddress((void**)&qphi, g_qphi);
    cudaGetSymbolAddress((void**)&kphi, g_kphi);
    cudaGetSymbolAddress((void**)&ckv,  g_ckv);
    cudaGetSymbolAddress((void**)&cat,  g_cat);

    const int smemKV  = (128 * 164 + 128 * 88) * 4;                 // 129024
    const int smemLin = (160 * 132 + 160 * 132 + 160 * 88) * 4;     // 225280
    const int smemSWA = (64 * 68 + 64 * 132 + 128 * 68 + 128 * 68) * 4; // 120832
    static bool attrs_set = false;
    if (!attrs_set) {
        cudaFuncSetAttribute(chunk_kv_v2, cudaFuncAttributeMaxDynamicSharedMemorySize, smemKV);
        cudaFuncSetAttribute(lin_attn_v3, cudaFuncAttributeMaxDynamicSharedMemorySize, smemLin);
        cudaFuncSetAttribute(swa_v3,      cudaFuncAttributeMaxDynamicSharedMemorySize, smemSWA);
        attrs_set = true;
    }

    rmsnorm_kernel<<<ROWS, 256>>>(x, norm_w, h);

    gemm_tf32<<<dim3(DMODEL / 128, ROWS / 128), 256>>>(h, Wq, q, nullptr, ROWS, DMODEL, DMODEL);
    gemm_tf32<<<dim3(DMODEL / 128, ROWS / 128), 256>>>(h, Wk, k, nullptr, ROWS, DMODEL, DMODEL);
    gemm_tf32<<<dim3(DMODEL / 128, ROWS / 128), 256>>>(h, Wv, v, nullptr, ROWS, DMODEL, DMODEL);

    feat_proj<<<HROWS / 16, 256>>>(q, Wqf, qf);
    feat_proj<<<HROWS / 16, 256>>>(k, Wkf, kf);

    taylor_phi<<<HROWS / 256, 256>>>(qf, qphi, HROWS);
    taylor_phi<<<HROWS / 256, 256>>>(kf, kphi, HROWS);

    chunk_kv_v2<<<BATCH * NH * NCHUNK, 320, smemKV>>>(kphi, v, ckv);
    prefix_kv_v2<<<(32 * FPAD * 72 + 255) / 256, 256>>>(ckv);
    lin_attn_v3<<<BATCH * NH * NCHUNK, 256, smemLin>>>(qphi, kphi, v, ckv, cat);

    swa_v3<<<dim3(SEQ / 64, NH, BATCH), 128, smemSWA>>>(q, k, v, cat);

    gemm_tf32<<<dim3(DMODEL / 128, ROWS / 128), 256>>>(cat, Wout, out, x, ROWS, DMODEL, 2 * DMODEL);
}

// round 4
// speedup vs baseline: 5.5270x; 1.5147x over previous
#include <cuda_runtime.h>
#include <cstdint>

#define BATCH 2
#define SEQ 2048
#define DMODEL 1024
#define NH 16
#define HD 64
#define FEAT 16
#define FDIM 153           // 1 + 16 + 136
#define FPAD 160
#define NCHUNK 16
#define CHUNKSZ 128
#define ROWS (BATCH*SEQ)          // 4096
#define HROWS (BATCH*SEQ*NH)      // 131072

// ------------------------- scratch (static device memory) -------------------
__device__ float g_h[ROWS*DMODEL];
__device__ float g_q[ROWS*DMODEL];
__device__ float g_k[ROWS*DMODEL];
__device__ float g_v[ROWS*DMODEL];
__device__ float g_ckv[(size_t)BATCH*NH*NCHUNK*FPAD*72];   // [bhc][160][72] (col64 = ksum)
__device__ float g_cat[(size_t)ROWS*2*DMODEL];

__device__ __forceinline__ uint32_t f2tf32(float f) {
    uint32_t u;
    asm("cvt.rna.tf32.f32 %0, %1;" : "=r"(u) : "f"(f));
    return u;
}

__device__ __forceinline__ void mma8(float acc[4], uint32_t a0, uint32_t a1,
                                     uint32_t a2, uint32_t a3,
                                     uint32_t b0, uint32_t b1) {
    asm volatile(
        "mma.sync.aligned.m16n8k8.row.col.f32.tf32.tf32.f32 "
        "{%0,%1,%2,%3}, {%4,%5,%6,%7}, {%8,%9}, {%0,%1,%2,%3};"
        : "+f"(acc[0]), "+f"(acc[1]), "+f"(acc[2]), "+f"(acc[3])
        : "r"(a0), "r"(a1), "r"(a2), "r"(a3), "r"(b0), "r"(b1));
}

__device__ __forceinline__ void cp16(uint32_t sdst, const float* gsrc) {
    asm volatile("cp.async.cg.shared.global [%0], [%1], 16;" :: "r"(sdst), "l"(gsrc));
}

// phi expansion: x[16] -> 160 features written dst[f*stride + tok] (raw fp32 bits)
__device__ __forceinline__ void write_phi_colmajor(uint32_t* dst, int tok, const float* xf) {
    float x[16];
    #pragma unroll
    for (int i = 0; i < 16; i++) x[i] = xf[i];
    dst[tok] = 0x3f800000u;
    #pragma unroll
    for (int i = 0; i < 16; i++) dst[(1 + i) * 132 + tok] = __float_as_uint(x[i]);
    const float inv = 0.70710678118654752440f;
    int idx = 17;
    #pragma unroll
    for (int i = 0; i < 16; i++) {
        dst[idx * 132 + tok] = __float_as_uint(0.5f * x[i] * x[i]); idx++;
        #pragma unroll
        for (int j = i + 1; j < 16; j++) {
            dst[idx * 132 + tok] = __float_as_uint(inv * x[i] * x[j]); idx++;
        }
    }
    #pragma unroll
    for (int f = FDIM; f < FPAD; f++) dst[f * 132 + tok] = 0u;
}

__device__ __forceinline__ void write_phi_rowmajor(uint32_t* dst, const float* xf) {
    float x[16];
    #pragma unroll
    for (int i = 0; i < 16; i++) x[i] = xf[i];
    dst[0] = 0x3f800000u;
    #pragma unroll
    for (int i = 0; i < 16; i++) dst[1 + i] = __float_as_uint(x[i]);
    const float inv = 0.70710678118654752440f;
    int idx = 17;
    #pragma unroll
    for (int i = 0; i < 16; i++) {
        dst[idx++] = __float_as_uint(0.5f * x[i] * x[i]);
        #pragma unroll
        for (int j = i + 1; j < 16; j++)
            dst[idx++] = __float_as_uint(inv * x[i] * x[j]);
    }
    #pragma unroll
    for (int f = FDIM; f < FPAD; f++) dst[f] = 0u;
}

// ------------------------------- RMSNorm ------------------------------------
__global__ void rmsnorm_kernel(const float* __restrict__ x,
                               const float* __restrict__ w,
                               float* __restrict__ h) {
    int row = blockIdx.x;
    const float* xr = x + (size_t)row * DMODEL;
    float s = 0.f;
    for (int i = threadIdx.x; i < DMODEL; i += 256) { float v = xr[i]; s += v * v; }
    __shared__ float red[8];
    #pragma unroll
    for (int o = 16; o > 0; o >>= 1) s += __shfl_xor_sync(0xffffffffu, s, o);
    if ((threadIdx.x & 31) == 0) red[threadIdx.x >> 5] = s;
    __syncthreads();
    if (threadIdx.x < 8) {
        float v = red[threadIdx.x];
        #pragma unroll
        for (int o = 4; o > 0; o >>= 1) v += __shfl_xor_sync(0xffu, v, o);
        if (threadIdx.x == 0) red[0] = v;
    }
    __syncthreads();
    float rs = rsqrtf(red[0] / (float)DMODEL + 1e-6f);
    float* hr = h + (size_t)row * DMODEL;
    for (int i = threadIdx.x; i < DMODEL; i += 256) hr[i] = xr[i] * rs * w[i];
}

// -------------- TF32 GEMM v2: cp.async 3-stage, raw-bit tf32 -----------------
// As[m][20] fp32, Bs[k][136] fp32. 128x128 tile, ktile=16.
#define AS_ELE (128*20)
#define BS_ELE (16*136)

__device__ __forceinline__ void gemm_issue(const float* A, const float* B,
        float* As, float* Bs, int bm, int bn, int k0, int K, int N, int tid) {
    int m = tid >> 1;
    int c0 = (tid & 1) * 2;
    const float* ga = A + (size_t)(bm + m) * K + k0 + c0 * 4;
    uint32_t sa = (uint32_t)__cvta_generic_to_shared(As + m * 20 + c0 * 4);
    cp16(sa, ga);
    cp16(sa + 16, ga + 4);
    #pragma unroll
    for (int j = 0; j < 2; j++) {
        int cc = tid + j * 256;
        int kk = cc >> 5, nc = cc & 31;
        const float* gb = B + (size_t)(k0 + kk) * N + bn + nc * 4;
        uint32_t sb = (uint32_t)__cvta_generic_to_shared(Bs + kk * 136 + nc * 4);
        cp16(sb, gb);
    }
}

__global__ __launch_bounds__(256) void gemm_v2(
        const float* __restrict__ A, const float* __restrict__ B,
        float* __restrict__ C, const float* __restrict__ residual,
        int M, int N, int K) {
    extern __shared__ float sg[];
    float* As = sg;                 // 3 stages
    float* Bs = sg + 3 * AS_ELE;
    int tid = threadIdx.x;
    int warp = tid >> 5, lane = tid & 31;
    int wm = (warp >> 2) * 64, wn = (warp & 3) * 32;
    int bm = blockIdx.y * 128, bn = blockIdx.x * 128;
    int r = lane >> 2, cq = lane & 3;

    float acc[4][4][4];
    #pragma unroll
    for (int mi = 0; mi < 4; mi++)
        #pragma unroll
        for (int ni = 0; ni < 4; ni++)
            #pragma unroll
            for (int e = 0; e < 4; e++) acc[mi][ni][e] = 0.f;

    int nk = K / 16;
    gemm_issue(A, B, As, Bs, bm, bn, 0, K, N, tid);
    asm volatile("cp.async.commit_group;");
    gemm_issue(A, B, As + AS_ELE, Bs + BS_ELE, bm, bn, 16, K, N, tid);
    asm volatile("cp.async.commit_group;");

    for (int kt = 0; kt < nk; kt++) {
        if (kt + 2 < nk) {
            int slot = (kt + 2) % 3;
            gemm_issue(A, B, As + slot * AS_ELE, Bs + slot * BS_ELE,
                       bm, bn, (kt + 2) * 16, K, N, tid);
        }
        asm volatile("cp.async.commit_group;");
        asm volatile("cp.async.wait_group 2;");
        __syncthreads();
        const uint32_t* Au = (const uint32_t*)(As + (kt % 3) * AS_ELE);
        const uint32_t* Bu = (const uint32_t*)(Bs + (kt % 3) * BS_ELE);
        #pragma unroll
        for (int ks = 0; ks < 16; ks += 8) {
            uint32_t af[4][4], bf[4][2];
            #pragma unroll
            for (int mi = 0; mi < 4; mi++) {
                int m = wm + mi * 16 + r;
                af[mi][0] = Au[m * 20 + ks + cq];
                af[mi][1] = Au[(m + 8) * 20 + ks + cq];
                af[mi][2] = Au[m * 20 + ks + cq + 4];
                af[mi][3] = Au[(m + 8) * 20 + ks + cq + 4];
            }
            #pragma unroll
            for (int ni = 0; ni < 4; ni++) {
                int n = wn + ni * 8 + r;
                bf[ni][0] = Bu[(ks + cq) * 136 + n];
                bf[ni][1] = Bu[(ks + cq + 4) * 136 + n];
            }
            #pragma unroll
            for (int mi = 0; mi < 4; mi++)
                #pragma unroll
                for (int ni = 0; ni < 4; ni++)
                    mma8(acc[mi][ni], af[mi][0], af[mi][1], af[mi][2], af[mi][3],
                         bf[ni][0], bf[ni][1]);
        }
        __syncthreads();
    }

    #pragma unroll
    for (int mi = 0; mi < 4; mi++) {
        int row0 = bm + wm + mi * 16 + r;
        #pragma unroll
        for (int ni = 0; ni < 4; ni++) {
            int col = bn + wn + ni * 8 + 2 * cq;
            float2 lo = make_float2(acc[mi][ni][0], acc[mi][ni][1]);
            float2 hi = make_float2(acc[mi][ni][2], acc[mi][ni][3]);
            if (residual) {
                float2 r0 = *(const float2*)(residual + (size_t)row0 * N + col);
                float2 r1 = *(const float2*)(residual + (size_t)(row0 + 8) * N + col);
                lo.x += r0.x; lo.y += r0.y; hi.x += r1.x; hi.y += r1.y;
            }
            *(float2*)(C + (size_t)row0 * N + col) = lo;
            *(float2*)(C + (size_t)(row0 + 8) * N + col) = hi;
        }
    }
}

// QKV fused: blockIdx.z selects which weight/output.
__global__ __launch_bounds__(256) void gemm_qkv(
        const float* __restrict__ A,
        const float* __restrict__ Bq, const float* __restrict__ Bk,
        const float* __restrict__ Bv,
        float* __restrict__ Cq, float* __restrict__ Ck, float* __restrict__ Cv) {
    extern __shared__ float sg[];
    const float* B = (blockIdx.z == 0) ? Bq : (blockIdx.z == 1) ? Bk : Bv;
    float* C = (blockIdx.z == 0) ? Cq : (blockIdx.z == 1) ? Ck : Cv;
    float* As = sg;
    float* Bs = sg + 3 * AS_ELE;
    int tid = threadIdx.x;
    int warp = tid >> 5, lane = tid & 31;
    int wm = (warp >> 2) * 64, wn = (warp & 3) * 32;
    int bm = blockIdx.y * 128, bn = blockIdx.x * 128;
    int r = lane >> 2, cq = lane & 3;
    const int K = DMODEL, N = DMODEL;

    float acc[4][4][4];
    #pragma unroll
    for (int mi = 0; mi < 4; mi++)
        #pragma unroll
        for (int ni = 0; ni < 4; ni++)
            #pragma unroll
            for (int e = 0; e < 4; e++) acc[mi][ni][e] = 0.f;

    int nk = K / 16;
    gemm_issue(A, B, As, Bs, bm, bn, 0, K, N, tid);
    asm volatile("cp.async.commit_group;");
    gemm_issue(A, B, As + AS_ELE, Bs + BS_ELE, bm, bn, 16, K, N, tid);
    asm volatile("cp.async.commit_group;");

    for (int kt = 0; kt < nk; kt++) {
        if (kt + 2 < nk) {
            int slot = (kt + 2) % 3;
            gemm_issue(A, B, As + slot * AS_ELE, Bs + slot * BS_ELE,
                       bm, bn, (kt + 2) * 16, K, N, tid);
        }
        asm volatile("cp.async.commit_group;");
        asm volatile("cp.async.wait_group 2;");
        __syncthreads();
        const uint32_t* Au = (const uint32_t*)(As + (kt % 3) * AS_ELE);
        const uint32_t* Bu = (const uint32_t*)(Bs + (kt % 3) * BS_ELE);
        #pragma unroll
        for (int ks = 0; ks < 16; ks += 8) {
            uint32_t af[4][4], bf[4][2];
            #pragma unroll
            for (int mi = 0; mi < 4; mi++) {
                int m = wm + mi * 16 + r;
                af[mi][0] = Au[m * 20 + ks + cq];
                af[mi][1] = Au[(m + 8) * 20 + ks + cq];
                af[mi][2] = Au[m * 20 + ks + cq + 4];
                af[mi][3] = Au[(m + 8) * 20 + ks + cq + 4];
            }
            #pragma unroll
            for (int ni = 0; ni < 4; ni++) {
                int n = wn + ni * 8 + r;
                bf[ni][0] = Bu[(ks + cq) * 136 + n];
                bf[ni][1] = Bu[(ks + cq + 4) * 136 + n];
            }
            #pragma unroll
            for (int mi = 0; mi < 4; mi++)
                #pragma unroll
                for (int ni = 0; ni < 4; ni++)
                    mma8(acc[mi][ni], af[mi][0], af[mi][1], af[mi][2], af[mi][3],
                         bf[ni][0], bf[ni][1]);
        }
        __syncthreads();
    }

    #pragma unroll
    for (int mi = 0; mi < 4; mi++) {
        int row0 = bm + wm + mi * 16 + r;
        #pragma unroll
        for (int ni = 0; ni < 4; ni++) {
            int col = bn + wn + ni * 8 + 2 * cq;
            *(float2*)(C + (size_t)row0 * N + col) =
                make_float2(acc[mi][ni][0], acc[mi][ni][1]);
            *(float2*)(C + (size_t)(row0 + 8) * N + col) =
                make_float2(acc[mi][ni][2], acc[mi][ni][3]);
        }
    }
}

// --------- pass A: fused feat-proj + phi + KV' = Kphi^T @ [V|1] ---------------
__global__ __launch_bounds__(320) void chunk_kv_v3(const float* __restrict__ kk_,
        const float* __restrict__ vv, const float* __restrict__ Wkf,
        float* __restrict__ ckv) {
    extern __shared__ uint32_t su[];
    uint32_t* Ks = su;              // [tok 128][feat 164] (phi, raw bits)
    uint32_t* Vs = su + 128 * 164;  // [tok 128][88]
    float* Kf = (float*)Ks;         // overlay: raw k tile [128][68]
    float* Sf = (float*)Vs;         // overlay: W [1024] + kf [2048]
    int tid = threadIdx.x, warp = tid >> 5, lane = tid & 31;
    int r = lane >> 2, cq = lane & 3;
    int bhc = blockIdx.x, c = bhc & 15, bh = bhc >> 4, b = bh >> 4, hh = bh & 15;
    size_t row0 = (size_t)(b * SEQ + c * CHUNKSZ) * DMODEL + hh * HD;

    for (int i = tid; i < 128 * 16; i += 320) {
        int tok = i >> 4, qd = (i & 15) * 4;
        float4 t = *(const float4*)(kk_ + row0 + (size_t)tok * DMODEL + qd);
        *(float4*)(Kf + tok * 68 + qd) = t;
    }
    for (int i = tid; i < 1024; i += 320) Sf[i] = Wkf[i];
    __syncthreads();

    if (tid < 128) {
        int tok = tid;
        float accf[16];
        #pragma unroll
        for (int cc = 0; cc < 16; cc++) accf[cc] = 0.f;
        for (int e = 0; e < 64; e++) {
            float rv = Kf[tok * 68 + e];
            #pragma unroll
            for (int cc = 0; cc < 16; cc++) accf[cc] += rv * Sf[e * 16 + cc];
        }
        #pragma unroll
        for (int cc = 0; cc < 16; cc++) Sf[1024 + tok * 16 + cc] = accf[cc];
    }
    __syncthreads();
    if (tid < 128) write_phi_rowmajor(Ks + tid * 164, Sf + 1024 + tid * 16);
    __syncthreads();

    for (int i = tid; i < 128 * 18; i += 320) {
        int tok = i / 18, qd = (i % 18) * 4;
        uint4 u = make_uint4(0u, 0u, 0u, 0u);
        if (qd < 64) {
            float4 t = *(const float4*)(vv + row0 + (size_t)tok * DMODEL + qd);
            u = make_uint4(__float_as_uint(t.x), __float_as_uint(t.y),
                           __float_as_uint(t.z), __float_as_uint(t.w));
        } else if (qd == 64) u.x = 0x3f800000u;
        *(uint4*)(Vs + tok * 88 + qd) = u;
    }
    __syncthreads();

    float acc[9][4];
    #pragma unroll
    for (int ni = 0; ni < 9; ni++)
        #pragma unroll
        for (int e = 0; e < 4; e++) acc[ni][e] = 0.f;
    int m0 = warp * 16;
    for (int kk = 0; kk < 128; kk += 8) {
        uint32_t a0 = Ks[(kk + cq) * 164 + m0 + r];
        uint32_t a1 = Ks[(kk + cq) * 164 + m0 + r + 8];
        uint32_t a2 = Ks[(kk + cq + 4) * 164 + m0 + r];
        uint32_t a3 = Ks[(kk + cq + 4) * 164 + m0 + r + 8];
        #pragma unroll
        for (int ni = 0; ni < 9; ni++) {
            uint32_t b0 = Vs[(kk + cq) * 88 + ni * 8 + r];
            uint32_t b1 = Vs[(kk + cq + 4) * 88 + ni * 8 + r];
            mma8(acc[ni], a0, a1, a2, a3, b0, b1);
        }
    }
    float* outb = ckv + (size_t)bhc * FPAD * 72;
    #pragma unroll
    for (int ni = 0; ni < 9; ni++) {
        int n = ni * 8 + 2 * cq;
        *(float2*)(outb + (m0 + r) * 72 + n)     = make_float2(acc[ni][0], acc[ni][1]);
        *(float2*)(outb + (m0 + r + 8) * 72 + n) = make_float2(acc[ni][2], acc[ni][3]);
    }
}

// --------------------- pass B: exclusive prefix over chunks ------------------
__global__ void prefix_kv_v2(float* __restrict__ ckv) {
    const int FD = FPAD * 72;
    int idx = blockIdx.x * 256 + threadIdx.x;
    if (idx >= 32 * FD) return;
    int bh = idx / FD, e = idx % FD;
    size_t base = (size_t)bh * NCHUNK * FD + e;
    float run = 0.f;
    for (int c = 0; c < NCHUNK; c++) {
        float cur = ckv[base + (size_t)c * FD];
        ckv[base + (size_t)c * FD] = run;
        run += cur;
    }
}

// --------- pass C: fused feat-proj + phi + linear attention (tf32) ------------
__global__ __launch_bounds__(256) void lin_attn_v4(const float* __restrict__ qq_,
        const float* __restrict__ kk_, const float* __restrict__ vv,
        const float* __restrict__ Wqf, const float* __restrict__ Wkf,
        const float* __restrict__ ckv, float* __restrict__ cat) {
    extern __shared__ uint32_t su[];
    uint32_t* Qs  = su;                    // [k 160][m 132]
    uint32_t* Ks  = su + 160 * 132;        // [k 160][n 132]
    uint32_t* KVs = Ks + 160 * 132;        // [k 160][n 88]
    uint32_t* Am  = Ks;                    // overlay
    uint32_t* Vs  = Ks + 128 * 132;        // overlay
    float* Qraw = (float*)Qs;              // [128][68]
    float* Kraw = (float*)Ks;              // [128][68]
    float* Scr  = (float*)KVs;             // W q[0..1023], W k[1024..2047], qf[2048..4095], kf[4096..6143]
    int tid = threadIdx.x, warp = tid >> 5, lane = tid & 31;
    int r = lane >> 2, cq = lane & 3;
    int bhc = blockIdx.x, c = bhc & 15, bh = bhc >> 4, b = bh >> 4, hh = bh & 15;
    size_t row0 = (size_t)(b * SEQ + c * CHUNKSZ) * DMODEL + hh * HD;

    for (int i = tid; i < 128 * 16; i += 256) {
        int tok = i >> 4, qd = (i & 15) * 4;
        *(float4*)(Qraw + tok * 68 + qd) =
            *(const float4*)(qq_ + row0 + (size_t)tok * DMODEL + qd);
        *(float4*)(Kraw + tok * 68 + qd) =
            *(const float4*)(kk_ + row0 + (size_t)tok * DMODEL + qd);
    }
    for (int i = tid; i < 1024; i += 256) { Scr[i] = Wqf[i]; Scr[1024 + i] = Wkf[i]; }
    __syncthreads();

    {
        int tok = tid & 127, which = tid >> 7;
        const float* raw = which ? Kraw : Qraw;
        const float* W   = Scr + which * 1024;
        float* of        = Scr + 2048 + which * 2048;
        float accf[16];
        #pragma unroll
        for (int cc = 0; cc < 16; cc++) accf[cc] = 0.f;
        for (int e = 0; e < 64; e++) {
            float rv = raw[tok * 68 + e];
            #pragma unroll
            for (int cc = 0; cc < 16; cc++) accf[cc] += rv * W[e * 16 + cc];
        }
        #pragma unroll
        for (int cc = 0; cc < 16; cc++) of[tok * 16 + cc] = accf[cc];
    }
    __syncthreads();
    {
        int tok = tid & 127, which = tid >> 7;
        uint32_t* dst = which ? Ks : Qs;
        write_phi_colmajor(dst, tok, Scr + 2048 + which * 2048 + tok * 16);
    }
    __syncthreads();

    const float* kvb = ckv + (size_t)bhc * FPAD * 72;
    for (int i = tid; i < 160 * 36; i += 256) {
        int f = i / 36, n = (i % 36) * 2;
        float2 t = *(const float2*)(kvb + f * 72 + n);
        KVs[f * 88 + n]     = __float_as_uint(t.x);
        KVs[f * 88 + n + 1] = __float_as_uint(t.y);
    }
    __syncthreads();

    // GEMM2: Y1z = Qphi @ KV'
    float accy[9][4];
    #pragma unroll
    for (int ni = 0; ni < 9; ni++)
        #pragma unroll
        for (int e = 0; e < 4; e++) accy[ni][e] = 0.f;
    int m0 = warp * 16;
    for (int kk = 0; kk < 160; kk += 8) {
        uint32_t a0 = Qs[(kk + cq) * 132 + m0 + r];
        uint32_t a1 = Qs[(kk + cq) * 132 + m0 + r + 8];
        uint32_t a2 = Qs[(kk + cq + 4) * 132 + m0 + r];
        uint32_t a3 = Qs[(kk + cq + 4) * 132 + m0 + r + 8];
        #pragma unroll
        for (int ni = 0; ni < 9; ni++) {
            uint32_t b0 = KVs[(kk + cq) * 88 + ni * 8 + r];
            uint32_t b1 = KVs[(kk + cq + 4) * 88 + ni * 8 + r];
            mma8(accy[ni], a0, a1, a2, a3, b0, b1);
        }
    }

    // GEMM1: S = Qphi @ Kphi^T
    float acc1[4][4][4];
    #pragma unroll
    for (int mi = 0; mi < 4; mi++)
        #pragma unroll
        for (int ni = 0; ni < 4; ni++)
            #pragma unroll
            for (int e = 0; e < 4; e++) acc1[mi][ni][e] = 0.f;
    int wm = (warp >> 2) * 64, wn = (warp & 3) * 32;
    for (int kk = 0; kk < 160; kk += 8) {
        uint32_t af[4][4];
        #pragma unroll
        for (int mi = 0; mi < 4; mi++) {
            int m = wm + mi * 16;
            af[mi][0] = Qs[(kk + cq) * 132 + m + r];
            af[mi][1] = Qs[(kk + cq) * 132 + m + r + 8];
            af[mi][2] = Qs[(kk + cq + 4) * 132 + m + r];
            af[mi][3] = Qs[(kk + cq + 4) * 132 + m + r + 8];
        }
        #pragma unroll
        for (int ni = 0; ni < 4; ni++) {
            uint32_t b0 = Ks[(kk + cq) * 132 + wn + ni * 8 + r];
            uint32_t b1 = Ks[(kk + cq + 4) * 132 + wn + ni * 8 + r];
            #pragma unroll
            for (int mi = 0; mi < 4; mi++)
                mma8(acc1[mi][ni], af[mi][0], af[mi][1], af[mi][2], af[mi][3], b0, b1);
        }
    }
    __syncthreads();

    // masked A (transposed) + V' into overlays
    #pragma unroll
    for (int mi = 0; mi < 4; mi++) {
        int row = wm + mi * 16 + r;
        #pragma unroll
        for (int ni = 0; ni < 4; ni++) {
            int col = wn + ni * 8 + 2 * cq;
            Am[col * 132 + row]           = (col     <= row)     ? __float_as_uint(acc1[mi][ni][0]) : 0u;
            Am[(col + 1) * 132 + row]     = (col + 1 <= row)     ? __float_as_uint(acc1[mi][ni][1]) : 0u;
            Am[col * 132 + row + 8]       = (col     <= row + 8) ? __float_as_uint(acc1[mi][ni][2]) : 0u;
            Am[(col + 1) * 132 + row + 8] = (col + 1 <= row + 8) ? __float_as_uint(acc1[mi][ni][3]) : 0u;
        }
    }
    for (int i = tid; i < 128 * 18; i += 256) {
        int tok = i / 18, qd = (i % 18) * 4;
        uint4 u = make_uint4(0u, 0u, 0u, 0u);
        if (qd < 64) {
            float4 t = *(const float4*)(vv + row0 + (size_t)tok * DMODEL + qd);
            u = make_uint4(__float_as_uint(t.x), __float_as_uint(t.y),
                           __float_as_uint(t.z), __float_as_uint(t.w));
        } else if (qd == 64) u.x = 0x3f800000u;
        *(uint4*)(Vs + tok * 88 + qd) = u;
    }
    __syncthreads();

    // GEMM3: accy += A @ V'
    for (int kk = 0; kk < 128; kk += 8) {
        uint32_t a0 = Am[(kk + cq) * 132 + m0 + r];
        uint32_t a1 = Am[(kk + cq) * 132 + m0 + r + 8];
        uint32_t a2 = Am[(kk + cq + 4) * 132 + m0 + r];
        uint32_t a3 = Am[(kk + cq + 4) * 132 + m0 + r + 8];
        #pragma unroll
        for (int ni = 0; ni < 9; ni++) {
            uint32_t b0 = Vs[(kk + cq) * 88 + ni * 8 + r];
            uint32_t b1 = Vs[(kk + cq + 4) * 88 + ni * 8 + r];
            mma8(accy[ni], a0, a1, a2, a3, b0, b1);
        }
    }

    float zlo = __shfl_sync(0xffffffffu, accy[8][0], lane & 28) + 1e-6f;
    float zhi = __shfl_sync(0xffffffffu, accy[8][2], lane & 28) + 1e-6f;
    float izlo = 1.f / zlo, izhi = 1.f / zhi;
    size_t rowg = (size_t)(b * SEQ + c * CHUNKSZ + m0 + r);
    #pragma unroll
    for (int ni = 0; ni < 8; ni++) {
        int colg = hh * HD + ni * 8 + 2 * cq;
        *(float2*)(cat + rowg * (2 * DMODEL) + colg) =
            make_float2(accy[ni][0] * izlo, accy[ni][1] * izlo);
        *(float2*)(cat + (rowg + 8) * (2 * DMODEL) + colg) =
            make_float2(accy[ni][2] * izhi, accy[ni][3] * izhi);
    }
}

// ------------------- sliding-window attention (tf32 mma) ---------------------
__global__ __launch_bounds__(128) void swa_v3(const float* __restrict__ q,
        const float* __restrict__ k, const float* __restrict__ v,
        float* __restrict__ cat) {
    extern __shared__ uint32_t su[];
    uint32_t* Qs = su;               // [e 64][tok 68]
    uint32_t* Ks = Qs + 64 * 68;     // [e 64][key 132]
    uint32_t* Ps = Ks + 64 * 132;    // [key 128][tok 68]
    uint32_t* Vs = Ps + 128 * 68;    // [key 128][d 68]
    int tid = threadIdx.x, warp = tid >> 5, lane = tid & 31;
    int r = lane >> 2, cq = lane & 3;
    int q0 = blockIdx.x * 64, hh = blockIdx.y, b = blockIdx.z;

    for (int i = tid; i < 64 * 16; i += 128) {
        int tok = i >> 4, qd = (i & 15) * 4;
        float4 t = *(const float4*)(q + (size_t)(b * SEQ + q0 + tok) * DMODEL + hh * HD + qd);
        Qs[(qd + 0) * 68 + tok] = __float_as_uint(t.x);
        Qs[(qd + 1) * 68 + tok] = __float_as_uint(t.y);
        Qs[(qd + 2) * 68 + tok] = __float_as_uint(t.z);
        Qs[(qd + 3) * 68 + tok] = __float_as_uint(t.w);
    }
    for (int i = tid; i < 128 * 16; i += 128) {
        int key = i >> 4, qd = (i & 15) * 4;
        int kg = q0 - 64 + key;
        float4 tk = make_float4(0.f, 0.f, 0.f, 0.f);
        float4 tv = make_float4(0.f, 0.f, 0.f, 0.f);
        if (kg >= 0) {
            tk = *(const float4*)(k + (size_t)(b * SEQ + kg) * DMODEL + hh * HD + qd);
            tv = *(const float4*)(v + (size_t)(b * SEQ + kg) * DMODEL + hh * HD + qd);
        }
        Ks[(qd + 0) * 132 + key] = __float_as_uint(tk.x);
        Ks[(qd + 1) * 132 + key] = __float_as_uint(tk.y);
        Ks[(qd + 2) * 132 + key] = __float_as_uint(tk.z);
        Ks[(qd + 3) * 132 + key] = __float_as_uint(tk.w);
        *(uint4*)(Vs + key * 68 + qd) =
            make_uint4(__float_as_uint(tv.x), __float_as_uint(tv.y),
                       __float_as_uint(tv.z), __float_as_uint(tv.w));
    }
    __syncthreads();

    float acc[16][4];
    #pragma unroll
    for (int ni = 0; ni < 16; ni++)
        #pragma unroll
        for (int e = 0; e < 4; e++) acc[ni][e] = 0.f;
    int m0 = warp * 16;
    for (int kk = 0; kk < 64; kk += 8) {
        uint32_t a0 = Qs[(kk + cq) * 68 + m0 + r];
        uint32_t a1 = Qs[(kk + cq) * 68 + m0 + r + 8];
        uint32_t a2 = Qs[(kk + cq + 4) * 68 + m0 + r];
        uint32_t a3 = Qs[(kk + cq + 4) * 68 + m0 + r + 8];
        #pragma unroll
        for (int ni = 0; ni < 16; ni++) {
            uint32_t b0 = Ks[(kk + cq) * 132 + ni * 8 + r];
            uint32_t b1 = Ks[(kk + cq + 4) * 132 + ni * 8 + r];
            mma8(acc[ni], a0, a1, a2, a3, b0, b1);
        }
    }

    int rowlo = m0 + r, rowhi = rowlo + 8;
    float mlo = -1e30f, mhi = -1e30f;
    #pragma unroll
    for (int ni = 0; ni < 16; ni++) {
        int n = ni * 8 + 2 * cq;
        bool ok0l = (n     >= rowlo) && (n     <= rowlo + 64) && (q0 - 64 + n     >= 0);
        bool ok1l = (n + 1 >= rowlo) && (n + 1 <= rowlo + 64) && (q0 - 64 + n + 1 >= 0);
        bool ok0h = (n     >= rowhi) && (n     <= rowhi + 64) && (q0 - 64 + n     >= 0);
        bool ok1h = (n + 1 >= rowhi) && (n + 1 <= rowhi + 64) && (q0 - 64 + n + 1 >= 0);
        acc[ni][0] = ok0l ? acc[ni][0] * 0.125f : -1e30f;
        acc[ni][1] = ok1l ? acc[ni][1] * 0.125f : -1e30f;
        acc[ni][2] = ok0h ? acc[ni][2] * 0.125f : -1e30f;
        acc[ni][3] = ok1h ? acc[ni][3] * 0.125f : -1e30f;
        mlo = fmaxf(mlo, fmaxf(acc[ni][0], acc[ni][1]));
        mhi = fmaxf(mhi, fmaxf(acc[ni][2], acc[ni][3]));
    }
    mlo = fmaxf(mlo, __shfl_xor_sync(0xffffffffu, mlo, 1));
    mlo = fmaxf(mlo, __shfl_xor_sync(0xffffffffu, mlo, 2));
    mhi = fmaxf(mhi, __shfl_xor_sync(0xffffffffu, mhi, 1));
    mhi = fmaxf(mhi, __shfl_xor_sync(0xffffffffu, mhi, 2));

    float slo = 0.f, shi = 0.f;
    #pragma unroll
    for (int ni = 0; ni < 16; ni++) {
        acc[ni][0] = __expf(acc[ni][0] - mlo);
        acc[ni][1] = __expf(acc[ni][1] - mlo);
        acc[ni][2] = __expf(acc[ni][2] - mhi);
        acc[ni][3] = __expf(acc[ni][3] - mhi);
        slo += acc[ni][0] + acc[ni][1];
        shi += acc[ni][2] + acc[ni][3];
    }
    slo += __shfl_xor_sync(0xffffffffu, slo, 1);
    slo += __shfl_xor_sync(0xffffffffu, slo, 2);
    shi += __shfl_xor_sync(0xffffffffu, shi, 1);
    shi += __shfl_xor_sync(0xffffffffu, shi, 2);

    #pragma unroll
    for (int ni = 0; ni < 16; ni++) {
        int n = ni * 8 + 2 * cq;
        Ps[n * 68 + rowlo]       = __float_as_uint(acc[ni][0]);
        Ps[(n + 1) * 68 + rowlo] = __float_as_uint(acc[ni][1]);
        Ps[n * 68 + rowhi]       = __float_as_uint(acc[ni][2]);
        Ps[(n + 1) * 68 + rowhi] = __float_as_uint(acc[ni][3]);
    }
    __syncwarp();

    float accO[8][4];
    #pragma unroll
    for (int ni = 0; ni < 8; ni++)
        #pragma unroll
        for (int e = 0; e < 4; e++) accO[ni][e] = 0.f;
    for (int kk = 0; kk < 128; kk += 8) {
        uint32_t a0 = Ps[(kk + cq) * 68 + m0 + r];
        uint32_t a1 = Ps[(kk + cq) * 68 + m0 + r + 8];
        uint32_t a2 = Ps[(kk + cq + 4) * 68 + m0 + r];
        uint32_t a3 = Ps[(kk + cq + 4) * 68 + m0 + r + 8];
        #pragma unroll
        for (int ni = 0; ni < 8; ni++) {
            uint32_t b0 = Vs[(kk + cq) * 68 + ni * 8 + r];
            uint32_t b1 = Vs[(kk + cq + 4) * 68 + ni * 8 + r];
            mma8(accO[ni], a0, a1, a2, a3, b0, b1);
        }
    }
    float izlo = 1.f / slo, izhi = 1.f / shi;
    #pragma unroll
    for (int ni = 0; ni < 8; ni++) {
        int colg = DMODEL + hh * HD + ni * 8 + 2 * cq;
        *(float2*)(cat + (size_t)(b * SEQ + q0 + rowlo) * (2 * DMODEL) + colg) =
            make_float2(accO[ni][0] * izlo, accO[ni][1] * izlo);
        *(float2*)(cat + (size_t)(b * SEQ + q0 + rowhi) * (2 * DMODEL) + colg) =
            make_float2(accO[ni][2] * izhi, accO[ni][3] * izhi);
    }
}

// ---------------------------------- launch -----------------------------------
extern "C" void kernel_launch(void* const* d_in, const int* in_sizes, int n_in,
                              void* d_out, int out_size) {
    const float* x      = (const float*)d_in[0];
    const float* norm_w = (const float*)d_in[1];
    const float* Wq     = (const float*)d_in[2];
    const float* Wk     = (const float*)d_in[3];
    const float* Wv     = (const float*)d_in[4];
    const float* Wqf    = (const float*)d_in[5];
    const float* Wkf    = (const float*)d_in[6];
    const float* Wout   = (const float*)d_in[7];
    float* out = (float*)d_out;

    float *h, *q, *k, *v, *ckv, *cat;
    cudaGetSymbolAddress((void**)&h,   g_h);
    cudaGetSymbolAddress((void**)&q,   g_q);
    cudaGetSymbolAddress((void**)&k,   g_k);
    cudaGetSymbolAddress((void**)&v,   g_v);
    cudaGetSymbolAddress((void**)&ckv, g_ckv);
    cudaGetSymbolAddress((void**)&cat, g_cat);

    const int smemG   = 3 * (AS_ELE + BS_ELE) * 4;                      // 56832
    const int smemKV  = (128 * 164 + 128 * 88) * 4;                     // 129024
    const int smemLin = (160 * 132 + 160 * 132 + 160 * 88) * 4;         // 225280
    const int smemSWA = (64 * 68 + 64 * 132 + 128 * 68 + 128 * 68) * 4; // 120832
    static bool attrs_set = false;
    if (!attrs_set) {
        cudaFuncSetAttribute(gemm_v2,     cudaFuncAttributeMaxDynamicSharedMemorySize, smemG);
        cudaFuncSetAttribute(gemm_qkv,    cudaFuncAttributeMaxDynamicSharedMemorySize, smemG);
        cudaFuncSetAttribute(chunk_kv_v3, cudaFuncAttributeMaxDynamicSharedMemorySize, smemKV);
        cudaFuncSetAttribute(lin_attn_v4, cudaFuncAttributeMaxDynamicSharedMemorySize, smemLin);
        cudaFuncSetAttribute(swa_v3,      cudaFuncAttributeMaxDynamicSharedMemorySize, smemSWA);
        attrs_set = true;
    }

    rmsnorm_kernel<<<ROWS, 256>>>(x, norm_w, h);

    gemm_qkv<<<dim3(DMODEL / 128, ROWS / 128, 3), 256, smemG>>>(h, Wq, Wk, Wv, q, k, v);

    chunk_kv_v3<<<BATCH * NH * NCHUNK, 320, smemKV>>>(k, v, Wkf, ckv);
    prefix_kv_v2<<<(32 * FPAD * 72 + 255) / 256, 256>>>(ckv);
    lin_attn_v4<<<BATCH * NH * NCHUNK, 256, smemLin>>>(q, k, v, Wqf, Wkf, ckv, cat);

    swa_v3<<<dim3(SEQ / 64, NH, BATCH), 128, smemSWA>>>(q, k, v, cat);

    gemm_v2<<<dim3(DMODEL / 128, ROWS / 128), 256, smemG>>>(cat, Wout, out, x, ROWS, DMODEL, 2 * DMODEL);
}

// round 5
// speedup vs baseline: 5.8281x; 1.0545x over previous
#include <cuda_runtime.h>
#include <cstdint>

#define BATCH 2
#define SEQ 2048
#define DMODEL 1024
#define NH 16
#define HD 64
#define FEAT 16
#define FDIM 153           // 1 + 16 + 136
#define FPAD 160
#define NCHUNK 16
#define CHUNKSZ 128
#define ROWS (BATCH*SEQ)          // 4096
#define HROWS (BATCH*SEQ*NH)      // 131072

// ------------------------- scratch (static device memory) -------------------
__device__ float g_h[ROWS*DMODEL];
__device__ float g_q[ROWS*DMODEL];
__device__ float g_k[ROWS*DMODEL];
__device__ float g_v[ROWS*DMODEL];
__device__ float g_ckv[(size_t)BATCH*NH*NCHUNK*FPAD*72];   // [bhc][160][72] (col64 = ksum)
__device__ float g_cat[(size_t)ROWS*2*DMODEL];

__device__ __forceinline__ void mma8(float acc[4], uint32_t a0, uint32_t a1,
                                     uint32_t a2, uint32_t a3,
                                     uint32_t b0, uint32_t b1) {
    asm volatile(
        "mma.sync.aligned.m16n8k8.row.col.f32.tf32.tf32.f32 "
        "{%0,%1,%2,%3}, {%4,%5,%6,%7}, {%8,%9}, {%0,%1,%2,%3};"
        : "+f"(acc[0]), "+f"(acc[1]), "+f"(acc[2]), "+f"(acc[3])
        : "r"(a0), "r"(a1), "r"(a2), "r"(a3), "r"(b0), "r"(b1));
}

__device__ __forceinline__ void cp16(uint32_t sdst, const float* gsrc) {
    asm volatile("cp.async.cg.shared.global [%0], [%1], 16;" :: "r"(sdst), "l"(gsrc));
}

// phi expansion: x[16] -> 160 features written dst[f*132 + tok] (raw fp32 bits)
__device__ __forceinline__ void write_phi_colmajor(uint32_t* dst, int tok, const float* xf) {
    float x[16];
    #pragma unroll
    for (int i = 0; i < 16; i++) x[i] = xf[i];
    dst[tok] = 0x3f800000u;
    #pragma unroll
    for (int i = 0; i < 16; i++) dst[(1 + i) * 132 + tok] = __float_as_uint(x[i]);
    const float inv = 0.70710678118654752440f;
    int idx = 17;
    #pragma unroll
    for (int i = 0; i < 16; i++) {
        dst[idx * 132 + tok] = __float_as_uint(0.5f * x[i] * x[i]); idx++;
        #pragma unroll
        for (int j = i + 1; j < 16; j++) {
            dst[idx * 132 + tok] = __float_as_uint(inv * x[i] * x[j]); idx++;
        }
    }
    #pragma unroll
    for (int f = FDIM; f < FPAD; f++) dst[f * 132 + tok] = 0u;
}

__device__ __forceinline__ void write_phi_rowmajor(uint32_t* dst, const float* xf) {
    float x[16];
    #pragma unroll
    for (int i = 0; i < 16; i++) x[i] = xf[i];
    dst[0] = 0x3f800000u;
    #pragma unroll
    for (int i = 0; i < 16; i++) dst[1 + i] = __float_as_uint(x[i]);
    const float inv = 0.70710678118654752440f;
    int idx = 17;
    #pragma unroll
    for (int i = 0; i < 16; i++) {
        dst[idx++] = __float_as_uint(0.5f * x[i] * x[i]);
        #pragma unroll
        for (int j = i + 1; j < 16; j++)
            dst[idx++] = __float_as_uint(inv * x[i] * x[j]);
    }
    #pragma unroll
    for (int f = FDIM; f < FPAD; f++) dst[f] = 0u;
}

// ------------------------------- RMSNorm ------------------------------------
__global__ void rmsnorm_kernel(const float* __restrict__ x,
                               const float* __restrict__ w,
                               float* __restrict__ h) {
    int row = blockIdx.x;
    const float* xr = x + (size_t)row * DMODEL;
    float s = 0.f;
    for (int i = threadIdx.x; i < DMODEL; i += 256) { float v = xr[i]; s += v * v; }
    __shared__ float red[8];
    #pragma unroll
    for (int o = 16; o > 0; o >>= 1) s += __shfl_xor_sync(0xffffffffu, s, o);
    if ((threadIdx.x & 31) == 0) red[threadIdx.x >> 5] = s;
    __syncthreads();
    if (threadIdx.x < 8) {
        float v = red[threadIdx.x];
        #pragma unroll
        for (int o = 4; o > 0; o >>= 1) v += __shfl_xor_sync(0xffu, v, o);
        if (threadIdx.x == 0) red[0] = v;
    }
    __syncthreads();
    float rs = rsqrtf(red[0] / (float)DMODEL + 1e-6f);
    float* hr = h + (size_t)row * DMODEL;
    for (int i = threadIdx.x; i < DMODEL; i += 256) hr[i] = xr[i] * rs * w[i];
}

// -------------- TF32 GEMM: cp.async 4-stage, raw-bit tf32 --------------------
#define AS_ELE (128*20)
#define BS_ELE (16*136)
#define NSTAGE 4

__device__ __forceinline__ void gemm_issue(const float* A, const float* B,
        float* As, float* Bs, int bm, int bn, int k0, int K, int N, int tid) {
    int m = tid >> 1;
    int c0 = (tid & 1) * 2;
    const float* ga = A + (size_t)(bm + m) * K + k0 + c0 * 4;
    uint32_t sa = (uint32_t)__cvta_generic_to_shared(As + m * 20 + c0 * 4);
    cp16(sa, ga);
    cp16(sa + 16, ga + 4);
    #pragma unroll
    for (int j = 0; j < 2; j++) {
        int cc = tid + j * 256;
        int kk = cc >> 5, nc = cc & 31;
        const float* gb = B + (size_t)(k0 + kk) * N + bn + nc * 4;
        uint32_t sb = (uint32_t)__cvta_generic_to_shared(Bs + kk * 136 + nc * 4);
        cp16(sb, gb);
    }
}

__device__ __forceinline__ void gemm_core(const float* A, const float* B, float* C,
        const float* residual, float* As, float* Bs, int bm, int bn, int K, int N,
        int tid) {
    int warp = tid >> 5, lane = tid & 31;
    int wm = (warp >> 2) * 64, wn = (warp & 3) * 32;
    int r = lane >> 2, cq = lane & 3;

    float acc[4][4][4];
    #pragma unroll
    for (int mi = 0; mi < 4; mi++)
        #pragma unroll
        for (int ni = 0; ni < 4; ni++)
            #pragma unroll
            for (int e = 0; e < 4; e++) acc[mi][ni][e] = 0.f;

    int nk = K / 16;
    gemm_issue(A, B, As, Bs, bm, bn, 0, K, N, tid);
    asm volatile("cp.async.commit_group;");
    gemm_issue(A, B, As + AS_ELE, Bs + BS_ELE, bm, bn, 16, K, N, tid);
    asm volatile("cp.async.commit_group;");
    gemm_issue(A, B, As + 2 * AS_ELE, Bs + 2 * BS_ELE, bm, bn, 32, K, N, tid);
    asm volatile("cp.async.commit_group;");

    for (int kt = 0; kt < nk; kt++) {
        if (kt + 3 < nk) {
            int slot = (kt + 3) & 3;
            gemm_issue(A, B, As + slot * AS_ELE, Bs + slot * BS_ELE,
                       bm, bn, (kt + 3) * 16, K, N, tid);
        }
        asm volatile("cp.async.commit_group;");
        asm volatile("cp.async.wait_group 3;");
        __syncthreads();
        const uint32_t* Au = (const uint32_t*)(As + (kt & 3) * AS_ELE);
        const uint32_t* Bu = (const uint32_t*)(Bs + (kt & 3) * BS_ELE);
        #pragma unroll
        for (int ks = 0; ks < 16; ks += 8) {
            uint32_t af[4][4], bf[4][2];
            #pragma unroll
            for (int mi = 0; mi < 4; mi++) {
                int m = wm + mi * 16 + r;
                af[mi][0] = Au[m * 20 + ks + cq];
                af[mi][1] = Au[(m + 8) * 20 + ks + cq];
                af[mi][2] = Au[m * 20 + ks + cq + 4];
                af[mi][3] = Au[(m + 8) * 20 + ks + cq + 4];
            }
            #pragma unroll
            for (int ni = 0; ni < 4; ni++) {
                int n = wn + ni * 8 + r;
                bf[ni][0] = Bu[(ks + cq) * 136 + n];
                bf[ni][1] = Bu[(ks + cq + 4) * 136 + n];
            }
            #pragma unroll
            for (int mi = 0; mi < 4; mi++)
                #pragma unroll
                for (int ni = 0; ni < 4; ni++)
                    mma8(acc[mi][ni], af[mi][0], af[mi][1], af[mi][2], af[mi][3],
                         bf[ni][0], bf[ni][1]);
        }
        __syncthreads();
    }

    #pragma unroll
    for (int mi = 0; mi < 4; mi++) {
        int row0 = bm + wm + mi * 16 + r;
        #pragma unroll
        for (int ni = 0; ni < 4; ni++) {
            int col = bn + wn + ni * 8 + 2 * cq;
            float2 lo = make_float2(acc[mi][ni][0], acc[mi][ni][1]);
            float2 hi = make_float2(acc[mi][ni][2], acc[mi][ni][3]);
            if (residual) {
                float2 r0 = *(const float2*)(residual + (size_t)row0 * N + col);
                float2 r1 = *(const float2*)(residual + (size_t)(row0 + 8) * N + col);
                lo.x += r0.x; lo.y += r0.y; hi.x += r1.x; hi.y += r1.y;
            }
            *(float2*)(C + (size_t)row0 * N + col) = lo;
            *(float2*)(C + (size_t)(row0 + 8) * N + col) = hi;
        }
    }
}

__global__ __launch_bounds__(256) void gemm_v2(
        const float* __restrict__ A, const float* __restrict__ B,
        float* __restrict__ C, const float* __restrict__ residual,
        int M, int N, int K) {
    extern __shared__ float sg[];
    gemm_core(A, B, C, residual, sg, sg + NSTAGE * AS_ELE,
              blockIdx.y * 128, blockIdx.x * 128, K, N, threadIdx.x);
}

__global__ __launch_bounds__(256) void gemm_qkv(
        const float* __restrict__ A,
        const float* __restrict__ Bq, const float* __restrict__ Bk,
        const float* __restrict__ Bv,
        float* __restrict__ Cq, float* __restrict__ Ck, float* __restrict__ Cv) {
    extern __shared__ float sg[];
    const float* B = (blockIdx.z == 0) ? Bq : (blockIdx.z == 1) ? Bk : Bv;
    float* C = (blockIdx.z == 0) ? Cq : (blockIdx.z == 1) ? Ck : Cv;
    gemm_core(A, B, C, nullptr, sg, sg + NSTAGE * AS_ELE,
              blockIdx.y * 128, blockIdx.x * 128, DMODEL, DMODEL, threadIdx.x);
}

// --------- pass A: fused feat-proj + phi + KV' = Kphi^T @ [V|1] ---------------
__global__ __launch_bounds__(320) void chunk_kv_v3(const float* __restrict__ kk_,
        const float* __restrict__ vv, const float* __restrict__ Wkf,
        float* __restrict__ ckv) {
    extern __shared__ uint32_t su[];
    uint32_t* Ks = su;              // [tok 128][feat 164]
    uint32_t* Vs = su + 128 * 164;  // [tok 128][88]
    float* Kf = (float*)Ks;         // overlay: raw k tile [128][68]
    float* Sf = (float*)Vs;         // overlay: W [1024] + kf [2048]
    int tid = threadIdx.x, warp = tid >> 5, lane = tid & 31;
    int r = lane >> 2, cq = lane & 3;
    int bhc = blockIdx.x, c = bhc & 15, bh = bhc >> 4, b = bh >> 4, hh = bh & 15;
    size_t row0 = (size_t)(b * SEQ + c * CHUNKSZ) * DMODEL + hh * HD;

    for (int i = tid; i < 128 * 16; i += 320) {
        int tok = i >> 4, qd = (i & 15) * 4;
        float4 t = *(const float4*)(kk_ + row0 + (size_t)tok * DMODEL + qd);
        *(float4*)(Kf + tok * 68 + qd) = t;
    }
    for (int i = tid; i < 1024; i += 320) Sf[i] = Wkf[i];
    __syncthreads();

    if (tid < 128) {
        int tok = tid;
        float accf[16];
        #pragma unroll
        for (int cc = 0; cc < 16; cc++) accf[cc] = 0.f;
        for (int e = 0; e < 64; e++) {
            float rv = Kf[tok * 68 + e];
            #pragma unroll
            for (int cc = 0; cc < 16; cc++) accf[cc] += rv * Sf[e * 16 + cc];
        }
        #pragma unroll
        for (int cc = 0; cc < 16; cc++) Sf[1024 + tok * 16 + cc] = accf[cc];
    }
    __syncthreads();
    if (tid < 128) write_phi_rowmajor(Ks + tid * 164, Sf + 1024 + tid * 16);
    __syncthreads();

    for (int i = tid; i < 128 * 18; i += 320) {
        int tok = i / 18, qd = (i % 18) * 4;
        uint4 u = make_uint4(0u, 0u, 0u, 0u);
        if (qd < 64) {
            float4 t = *(const float4*)(vv + row0 + (size_t)tok * DMODEL + qd);
            u = make_uint4(__float_as_uint(t.x), __float_as_uint(t.y),
                           __float_as_uint(t.z), __float_as_uint(t.w));
        } else if (qd == 64) u.x = 0x3f800000u;
        *(uint4*)(Vs + tok * 88 + qd) = u;
    }
    __syncthreads();

    float acc[9][4];
    #pragma unroll
    for (int ni = 0; ni < 9; ni++)
        #pragma unroll
        for (int e = 0; e < 4; e++) acc[ni][e] = 0.f;
    int m0 = warp * 16;
    for (int kk = 0; kk < 128; kk += 8) {
        uint32_t a0 = Ks[(kk + cq) * 164 + m0 + r];
        uint32_t a1 = Ks[(kk + cq) * 164 + m0 + r + 8];
        uint32_t a2 = Ks[(kk + cq + 4) * 164 + m0 + r];
        uint32_t a3 = Ks[(kk + cq + 4) * 164 + m0 + r + 8];
        #pragma unroll
        for (int ni = 0; ni < 9; ni++) {
            uint32_t b0 = Vs[(kk + cq) * 88 + ni * 8 + r];
            uint32_t b1 = Vs[(kk + cq + 4) * 88 + ni * 8 + r];
            mma8(acc[ni], a0, a1, a2, a3, b0, b1);
        }
    }
    float* outb = ckv + (size_t)bhc * FPAD * 72;
    #pragma unroll
    for (int ni = 0; ni < 9; ni++) {
        int n = ni * 8 + 2 * cq;
        *(float2*)(outb + (m0 + r) * 72 + n)     = make_float2(acc[ni][0], acc[ni][1]);
        *(float2*)(outb + (m0 + r + 8) * 72 + n) = make_float2(acc[ni][2], acc[ni][3]);
    }
}

// --------------------- pass B: exclusive prefix over chunks ------------------
__global__ void prefix_kv_v2(float* __restrict__ ckv) {
    const int FD = FPAD * 72;
    int idx = blockIdx.x * 256 + threadIdx.x;
    if (idx >= 32 * FD) return;
    int bh = idx / FD, e = idx % FD;
    size_t base = (size_t)bh * NCHUNK * FD + e;
    float run = 0.f;
    for (int c = 0; c < NCHUNK; c++) {
        float cur = ckv[base + (size_t)c * FD];
        ckv[base + (size_t)c * FD] = run;
        run += cur;
    }
}

// --------- pass C: fused feat-proj + phi + linear attention (tf32) ------------
__global__ __launch_bounds__(256) void lin_attn_v4(const float* __restrict__ qq_,
        const float* __restrict__ kk_, const float* __restrict__ vv,
        const float* __restrict__ Wqf, const float* __restrict__ Wkf,
        const float* __restrict__ ckv, float* __restrict__ cat) {
    extern __shared__ uint32_t su[];
    uint32_t* Qs  = su;                    // [k 160][m 132]
    uint32_t* Ks  = su + 160 * 132;        // [k 160][n 132]
    uint32_t* KVs = Ks + 160 * 132;        // [k 160][n 88]
    uint32_t* Am  = Ks;                    // overlay
    uint32_t* Vs  = Ks + 128 * 132;        // overlay
    float* Qraw = (float*)Qs;              // [128][68]
    float* Kraw = (float*)Ks;              // [128][68]
    float* Scr  = (float*)KVs;
    int tid = threadIdx.x, warp = tid >> 5, lane = tid & 31;
    int r = lane >> 2, cq = lane & 3;
    int bhc = blockIdx.x, c = bhc & 15, bh = bhc >> 4, b = bh >> 4, hh = bh & 15;
    size_t row0 = (size_t)(b * SEQ + c * CHUNKSZ) * DMODEL + hh * HD;

    for (int i = tid; i < 128 * 16; i += 256) {
        int tok = i >> 4, qd = (i & 15) * 4;
        *(float4*)(Qraw + tok * 68 + qd) =
            *(const float4*)(qq_ + row0 + (size_t)tok * DMODEL + qd);
        *(float4*)(Kraw + tok * 68 + qd) =
            *(const float4*)(kk_ + row0 + (size_t)tok * DMODEL + qd);
    }
    for (int i = tid; i < 1024; i += 256) { Scr[i] = Wqf[i]; Scr[1024 + i] = Wkf[i]; }
    __syncthreads();

    {
        int tok = tid & 127, which = tid >> 7;
        const float* raw = which ? Kraw : Qraw;
        const float* W   = Scr + which * 1024;
        float* of        = Scr + 2048 + which * 2048;
        float accf[16];
        #pragma unroll
        for (int cc = 0; cc < 16; cc++) accf[cc] = 0.f;
        for (int e = 0; e < 64; e++) {
            float rv = raw[tok * 68 + e];
            #pragma unroll
            for (int cc = 0; cc < 16; cc++) accf[cc] += rv * W[e * 16 + cc];
        }
        #pragma unroll
        for (int cc = 0; cc < 16; cc++) of[tok * 16 + cc] = accf[cc];
    }
    __syncthreads();
    {
        int tok = tid & 127, which = tid >> 7;
        uint32_t* dst = which ? Ks : Qs;
        write_phi_colmajor(dst, tok, Scr + 2048 + which * 2048 + tok * 16);
    }
    __syncthreads();

    const float* kvb = ckv + (size_t)bhc * FPAD * 72;
    for (int i = tid; i < 160 * 36; i += 256) {
        int f = i / 36, n = (i % 36) * 2;
        float2 t = *(const float2*)(kvb + f * 72 + n);
        KVs[f * 88 + n]     = __float_as_uint(t.x);
        KVs[f * 88 + n + 1] = __float_as_uint(t.y);
    }
    __syncthreads();

    float accy[9][4];
    #pragma unroll
    for (int ni = 0; ni < 9; ni++)
        #pragma unroll
        for (int e = 0; e < 4; e++) accy[ni][e] = 0.f;
    int m0 = warp * 16;
    for (int kk = 0; kk < 160; kk += 8) {
        uint32_t a0 = Qs[(kk + cq) * 132 + m0 + r];
        uint32_t a1 = Qs[(kk + cq) * 132 + m0 + r + 8];
        uint32_t a2 = Qs[(kk + cq + 4) * 132 + m0 + r];
        uint32_t a3 = Qs[(kk + cq + 4) * 132 + m0 + r + 8];
        #pragma unroll
        for (int ni = 0; ni < 9; ni++) {
            uint32_t b0 = KVs[(kk + cq) * 88 + ni * 8 + r];
            uint32_t b1 = KVs[(kk + cq + 4) * 88 + ni * 8 + r];
            mma8(accy[ni], a0, a1, a2, a3, b0, b1);
        }
    }

    float acc1[4][4][4];
    #pragma unroll
    for (int mi = 0; mi < 4; mi++)
        #pragma unroll
        for (int ni = 0; ni < 4; ni++)
            #pragma unroll
            for (int e = 0; e < 4; e++) acc1[mi][ni][e] = 0.f;
    int wm = (warp >> 2) * 64, wn = (warp & 3) * 32;
    for (int kk = 0; kk < 160; kk += 8) {
        uint32_t af[4][4];
        #pragma unroll
        for (int mi = 0; mi < 4; mi++) {
            int m = wm + mi * 16;
            af[mi][0] = Qs[(kk + cq) * 132 + m + r];
            af[mi][1] = Qs[(kk + cq) * 132 + m + r + 8];
            af[mi][2] = Qs[(kk + cq + 4) * 132 + m + r];
            af[mi][3] = Qs[(kk + cq + 4) * 132 + m + r + 8];
        }
        #pragma unroll
        for (int ni = 0; ni < 4; ni++) {
            uint32_t b0 = Ks[(kk + cq) * 132 + wn + ni * 8 + r];
            uint32_t b1 = Ks[(kk + cq + 4) * 132 + wn + ni * 8 + r];
            #pragma unroll
            for (int mi = 0; mi < 4; mi++)
                mma8(acc1[mi][ni], af[mi][0], af[mi][1], af[mi][2], af[mi][3], b0, b1);
        }
    }
    __syncthreads();

    #pragma unroll
    for (int mi = 0; mi < 4; mi++) {
        int row = wm + mi * 16 + r;
        #pragma unroll
        for (int ni = 0; ni < 4; ni++) {
            int col = wn + ni * 8 + 2 * cq;
            Am[col * 132 + row]           = (col     <= row)     ? __float_as_uint(acc1[mi][ni][0]) : 0u;
            Am[(col + 1) * 132 + row]     = (col + 1 <= row)     ? __float_as_uint(acc1[mi][ni][1]) : 0u;
            Am[col * 132 + row + 8]       = (col     <= row + 8) ? __float_as_uint(acc1[mi][ni][2]) : 0u;
            Am[(col + 1) * 132 + row + 8] = (col + 1 <= row + 8) ? __float_as_uint(acc1[mi][ni][3]) : 0u;
        }
    }
    for (int i = tid; i < 128 * 18; i += 256) {
        int tok = i / 18, qd = (i % 18) * 4;
        uint4 u = make_uint4(0u, 0u, 0u, 0u);
        if (qd < 64) {
            float4 t = *(const float4*)(vv + row0 + (size_t)tok * DMODEL + qd);
            u = make_uint4(__float_as_uint(t.x), __float_as_uint(t.y),
                           __float_as_uint(t.z), __float_as_uint(t.w));
        } else if (qd == 64) u.x = 0x3f800000u;
        *(uint4*)(Vs + tok * 88 + qd) = u;
    }
    __syncthreads();

    for (int kk = 0; kk < 128; kk += 8) {
        uint32_t a0 = Am[(kk + cq) * 132 + m0 + r];
        uint32_t a1 = Am[(kk + cq) * 132 + m0 + r + 8];
        uint32_t a2 = Am[(kk + cq + 4) * 132 + m0 + r];
        uint32_t a3 = Am[(kk + cq + 4) * 132 + m0 + r + 8];
        #pragma unroll
        for (int ni = 0; ni < 9; ni++) {
            uint32_t b0 = Vs[(kk + cq) * 88 + ni * 8 + r];
            uint32_t b1 = Vs[(kk + cq + 4) * 88 + ni * 8 + r];
            mma8(accy[ni], a0, a1, a2, a3, b0, b1);
        }
    }

    float zlo = __shfl_sync(0xffffffffu, accy[8][0], lane & 28) + 1e-6f;
    float zhi = __shfl_sync(0xffffffffu, accy[8][2], lane & 28) + 1e-6f;
    float izlo = 1.f / zlo, izhi = 1.f / zhi;
    size_t rowg = (size_t)(b * SEQ + c * CHUNKSZ + m0 + r);
    #pragma unroll
    for (int ni = 0; ni < 8; ni++) {
        int colg = hh * HD + ni * 8 + 2 * cq;
        *(float2*)(cat + rowg * (2 * DMODEL) + colg) =
            make_float2(accy[ni][0] * izlo, accy[ni][1] * izlo);
        *(float2*)(cat + (rowg + 8) * (2 * DMODEL) + colg) =
            make_float2(accy[ni][2] * izhi, accy[ni][3] * izhi);
    }
}

// ---------------- sliding-window attention (256 thr, warp-pair) --------------
__global__ __launch_bounds__(256) void swa_v4(const float* __restrict__ q,
        const float* __restrict__ k, const float* __restrict__ v,
        float* __restrict__ cat) {
    extern __shared__ uint32_t su[];
    uint32_t* Qs = su;               // [e 64][tok 68]
    uint32_t* Ks = Qs + 64 * 68;     // [e 64][key 132]
    uint32_t* Ps = Ks + 64 * 132;    // [key 128][tok 68]
    uint32_t* Vs = Ps + 128 * 68;    // [key 128][d 68]
    float* red   = (float*)(Vs + 128 * 68);  // max[64][2] then sum[64][2]
    float* Osm   = (float*)Qs;       // overlay after S phase: [row 64][68]
    int tid = threadIdx.x, warp = tid >> 5, lane = tid & 31;
    int r = lane >> 2, cq = lane & 3;
    int g = warp & 3, half = warp >> 2;
    int m0 = g * 16;
    int q0 = blockIdx.x * 64, hh = blockIdx.y, b = blockIdx.z;

    for (int i = tid; i < 64 * 16; i += 256) {
        int tok = i >> 4, qd = (i & 15) * 4;
        float4 t = *(const float4*)(q + (size_t)(b * SEQ + q0 + tok) * DMODEL + hh * HD + qd);
        Qs[(qd + 0) * 68 + tok] = __float_as_uint(t.x);
        Qs[(qd + 1) * 68 + tok] = __float_as_uint(t.y);
        Qs[(qd + 2) * 68 + tok] = __float_as_uint(t.z);
        Qs[(qd + 3) * 68 + tok] = __float_as_uint(t.w);
    }
    for (int i = tid; i < 128 * 16; i += 256) {
        int key = i >> 4, qd = (i & 15) * 4;
        int kg = q0 - 64 + key;
        float4 tk = make_float4(0.f, 0.f, 0.f, 0.f);
        float4 tv = make_float4(0.f, 0.f, 0.f, 0.f);
        if (kg >= 0) {
            tk = *(const float4*)(k + (size_t)(b * SEQ + kg) * DMODEL + hh * HD + qd);
            tv = *(const float4*)(v + (size_t)(b * SEQ + kg) * DMODEL + hh * HD + qd);
        }
        Ks[(qd + 0) * 132 + key] = __float_as_uint(tk.x);
        Ks[(qd + 1) * 132 + key] = __float_as_uint(tk.y);
        Ks[(qd + 2) * 132 + key] = __float_as_uint(tk.z);
        Ks[(qd + 3) * 132 + key] = __float_as_uint(tk.w);
        *(uint4*)(Vs + key * 68 + qd) =
            make_uint4(__float_as_uint(tv.x), __float_as_uint(tv.y),
                       __float_as_uint(tv.z), __float_as_uint(tv.w));
    }
    __syncthreads();

    // S = Q @ K^T : warp (g,half) does rows m0..m0+15, key tiles half*8..half*8+7
    float acc[8][4];
    #pragma unroll
    for (int ni = 0; ni < 8; ni++)
        #pragma unroll
        for (int e = 0; e < 4; e++) acc[ni][e] = 0.f;
    for (int kk = 0; kk < 64; kk += 8) {
        uint32_t a0 = Qs[(kk + cq) * 68 + m0 + r];
        uint32_t a1 = Qs[(kk + cq) * 68 + m0 + r + 8];
        uint32_t a2 = Qs[(kk + cq + 4) * 68 + m0 + r];
        uint32_t a3 = Qs[(kk + cq + 4) * 68 + m0 + r + 8];
        #pragma unroll
        for (int ni = 0; ni < 8; ni++) {
            int gn = half * 8 + ni;
            uint32_t b0 = Ks[(kk + cq) * 132 + gn * 8 + r];
            uint32_t b1 = Ks[(kk + cq + 4) * 132 + gn * 8 + r];
            mma8(acc[ni], a0, a1, a2, a3, b0, b1);
        }
    }

    int rowlo = m0 + r, rowhi = rowlo + 8;
    float mlo = -1e30f, mhi = -1e30f;
    #pragma unroll
    for (int ni = 0; ni < 8; ni++) {
        int n = (half * 8 + ni) * 8 + 2 * cq;
        bool ok0l = (n     >= rowlo) && (n     <= rowlo + 64) && (q0 - 64 + n     >= 0);
        bool ok1l = (n + 1 >= rowlo) && (n + 1 <= rowlo + 64) && (q0 - 64 + n + 1 >= 0);
        bool ok0h = (n     >= rowhi) && (n     <= rowhi + 64) && (q0 - 64 + n     >= 0);
        bool ok1h = (n + 1 >= rowhi) && (n + 1 <= rowhi + 64) && (q0 - 64 + n + 1 >= 0);
        acc[ni][0] = ok0l ? acc[ni][0] * 0.125f : -1e30f;
        acc[ni][1] = ok1l ? acc[ni][1] * 0.125f : -1e30f;
        acc[ni][2] = ok0h ? acc[ni][2] * 0.125f : -1e30f;
        acc[ni][3] = ok1h ? acc[ni][3] * 0.125f : -1e30f;
        mlo = fmaxf(mlo, fmaxf(acc[ni][0], acc[ni][1]));
        mhi = fmaxf(mhi, fmaxf(acc[ni][2], acc[ni][3]));
    }
    mlo = fmaxf(mlo, __shfl_xor_sync(0xffffffffu, mlo, 1));
    mlo = fmaxf(mlo, __shfl_xor_sync(0xffffffffu, mlo, 2));
    mhi = fmaxf(mhi, __shfl_xor_sync(0xffffffffu, mhi, 1));
    mhi = fmaxf(mhi, __shfl_xor_sync(0xffffffffu, mhi, 2));
    if (cq == 0) {
        red[rowlo * 2 + half] = mlo;
        red[rowhi * 2 + half] = mhi;
    }
    __syncthreads();
    float Mlo = fmaxf(red[rowlo * 2], red[rowlo * 2 + 1]);
    float Mhi = fmaxf(red[rowhi * 2], red[rowhi * 2 + 1]);

    float slo = 0.f, shi = 0.f;
    #pragma unroll
    for (int ni = 0; ni < 8; ni++) {
        acc[ni][0] = __expf(acc[ni][0] - Mlo);
        acc[ni][1] = __expf(acc[ni][1] - Mlo);
        acc[ni][2] = __expf(acc[ni][2] - Mhi);
        acc[ni][3] = __expf(acc[ni][3] - Mhi);
        slo += acc[ni][0] + acc[ni][1];
        shi += acc[ni][2] + acc[ni][3];
    }
    slo += __shfl_xor_sync(0xffffffffu, slo, 1);
    slo += __shfl_xor_sync(0xffffffffu, slo, 2);
    shi += __shfl_xor_sync(0xffffffffu, shi, 1);
    shi += __shfl_xor_sync(0xffffffffu, shi, 2);
    if (cq == 0) {
        red[128 + rowlo * 2 + half] = slo;
        red[128 + rowhi * 2 + half] = shi;
    }

    // store P into own (rows m0.., keys half*64..) region of Ps
    #pragma unroll
    for (int ni = 0; ni < 8; ni++) {
        int n = (half * 8 + ni) * 8 + 2 * cq;
        Ps[n * 68 + rowlo]       = __float_as_uint(acc[ni][0]);
        Ps[(n + 1) * 68 + rowlo] = __float_as_uint(acc[ni][1]);
        Ps[n * 68 + rowhi]       = __float_as_uint(acc[ni][2]);
        Ps[(n + 1) * 68 + rowhi] = __float_as_uint(acc[ni][3]);
    }
    __syncthreads();
    float sumlo = red[128 + rowlo * 2] + red[128 + rowlo * 2 + 1];
    float sumhi = red[128 + rowhi * 2] + red[128 + rowhi * 2 + 1];

    // O_partial = P(own key half) @ V
    float accO[8][4];
    #pragma unroll
    for (int ni = 0; ni < 8; ni++)
        #pragma unroll
        for (int e = 0; e < 4; e++) accO[ni][e] = 0.f;
    for (int ks = 0; ks < 64; ks += 8) {
        int kk = half * 64 + ks;
        uint32_t a0 = Ps[(kk + cq) * 68 + m0 + r];
        uint32_t a1 = Ps[(kk + cq) * 68 + m0 + r + 8];
        uint32_t a2 = Ps[(kk + cq + 4) * 68 + m0 + r];
        uint32_t a3 = Ps[(kk + cq + 4) * 68 + m0 + r + 8];
        #pragma unroll
        for (int ni = 0; ni < 8; ni++) {
            uint32_t b0 = Vs[(kk + cq) * 68 + ni * 8 + r];
            uint32_t b1 = Vs[(kk + cq + 4) * 68 + ni * 8 + r];
            mma8(accO[ni], a0, a1, a2, a3, b0, b1);
        }
    }
    if (half == 1) {
        #pragma unroll
        for (int ni = 0; ni < 8; ni++) {
            int n = ni * 8 + 2 * cq;
            Osm[rowlo * 68 + n]     = accO[ni][0];
            Osm[rowlo * 68 + n + 1] = accO[ni][1];
            Osm[rowhi * 68 + n]     = accO[ni][2];
            Osm[rowhi * 68 + n + 1] = accO[ni][3];
        }
    }
    __syncthreads();
    if (half == 0) {
        float izlo = 1.f / sumlo, izhi = 1.f / sumhi;
        #pragma unroll
        for (int ni = 0; ni < 8; ni++) {
            int n = ni * 8 + 2 * cq;
            int colg = DMODEL + hh * HD + n;
            *(float2*)(cat + (size_t)(b * SEQ + q0 + rowlo) * (2 * DMODEL) + colg) =
                make_float2((accO[ni][0] + Osm[rowlo * 68 + n]) * izlo,
                            (accO[ni][1] + Osm[rowlo * 68 + n + 1]) * izlo);
            *(float2*)(cat + (size_t)(b * SEQ + q0 + rowhi) * (2 * DMODEL) + colg) =
                make_float2((accO[ni][2] + Osm[rowhi * 68 + n]) * izhi,
                            (accO[ni][3] + Osm[rowhi * 68 + n + 1]) * izhi);
        }
    }
}

// ---------------------------------- launch -----------------------------------
extern "C" void kernel_launch(void* const* d_in, const int* in_sizes, int n_in,
                              void* d_out, int out_size) {
    const float* x      = (const float*)d_in[0];
    const float* norm_w = (const float*)d_in[1];
    const float* Wq     = (const float*)d_in[2];
    const float* Wk     = (const float*)d_in[3];
    const float* Wv     = (const float*)d_in[4];
    const float* Wqf    = (const float*)d_in[5];
    const float* Wkf    = (const float*)d_in[6];
    const float* Wout   = (const float*)d_in[7];
    float* out = (float*)d_out;

    float *h, *q, *k, *v, *ckv, *cat;
    cudaGetSymbolAddress((void**)&h,   g_h);
    cudaGetSymbolAddress((void**)&q,   g_q);
    cudaGetSymbolAddress((void**)&k,   g_k);
    cudaGetSymbolAddress((void**)&v,   g_v);
    cudaGetSymbolAddress((void**)&ckv, g_ckv);
    cudaGetSymbolAddress((void**)&cat, g_cat);

    const int smemG   = NSTAGE * (AS_ELE + BS_ELE) * 4;                 // 75776
    const int smemKV  = (128 * 164 + 128 * 88) * 4;                     // 129024
    const int smemLin = (160 * 132 + 160 * 132 + 160 * 88) * 4;         // 225280
    const int smemSWA = (64 * 68 + 64 * 132 + 128 * 68 + 128 * 68) * 4 + 256 * 4;
    static bool attrs_set = false;
    if (!attrs_set) {
        cudaFuncSetAttribute(gemm_v2,     cudaFuncAttributeMaxDynamicSharedMemorySize, smemG);
        cudaFuncSetAttribute(gemm_qkv,    cudaFuncAttributeMaxDynamicSharedMemorySize, smemG);
        cudaFuncSetAttribute(chunk_kv_v3, cudaFuncAttributeMaxDynamicSharedMemorySize, smemKV);
        cudaFuncSetAttribute(lin_attn_v4, cudaFuncAttributeMaxDynamicSharedMemorySize, smemLin);
        cudaFuncSetAttribute(swa_v4,      cudaFuncAttributeMaxDynamicSharedMemorySize, smemSWA);
        attrs_set = true;
    }

    rmsnorm_kernel<<<ROWS, 256>>>(x, norm_w, h);

    gemm_qkv<<<dim3(DMODEL / 128, ROWS / 128, 3), 256, smemG>>>(h, Wq, Wk, Wv, q, k, v);

    chunk_kv_v3<<<BATCH * NH * NCHUNK, 320, smemKV>>>(k, v, Wkf, ckv);
    prefix_kv_v2<<<(32 * FPAD * 72 + 255) / 256, 256>>>(ckv);
    lin_attn_v4<<<BATCH * NH * NCHUNK, 256, smemLin>>>(q, k, v, Wqf, Wkf, ckv, cat);

    swa_v4<<<dim3(SEQ / 64, NH, BATCH), 256, smemSWA>>>(q, k, v, cat);

    gemm_v2<<<dim3(DMODEL / 128, ROWS / 128), 256, smemG>>>(cat, Wout, out, x, ROWS, DMODEL, 2 * DMODEL);
}

// round 7
// speedup vs baseline: 6.4743x; 1.1109x over previous
#include <cuda_runtime.h>
#include <cstdint>

#define BATCH 2
#define SEQ 2048
#define DMODEL 1024
#define NH 16
#define HD 64
#define FEAT 16
#define FDIM 153           // 1 + 16 + 136
#define FPAD 160
#define NCHUNK 16
#define CHUNKSZ 128
#define ROWS (BATCH*SEQ)          // 4096
#define HROWS (BATCH*SEQ*NH)      // 131072

// ------------------------- scratch (static device memory) -------------------
__device__ float g_h[ROWS*DMODEL];
__device__ float g_q[ROWS*DMODEL];
__device__ float g_k[ROWS*DMODEL];
__device__ float g_v[ROWS*DMODEL];
__device__ float g_ckv[(size_t)BATCH*NH*NCHUNK*FPAD*72];   // [bhc][160][72] (col64 = ksum)
__device__ float g_cat[(size_t)ROWS*2*DMODEL];

__device__ __forceinline__ void mma8(float acc[4], uint32_t a0, uint32_t a1,
                                     uint32_t a2, uint32_t a3,
                                     uint32_t b0, uint32_t b1) {
    asm volatile(
        "mma.sync.aligned.m16n8k8.row.col.f32.tf32.tf32.f32 "
        "{%0,%1,%2,%3}, {%4,%5,%6,%7}, {%8,%9}, {%0,%1,%2,%3};"
        : "+f"(acc[0]), "+f"(acc[1]), "+f"(acc[2]), "+f"(acc[3])
        : "r"(a0), "r"(a1), "r"(a2), "r"(a3), "r"(b0), "r"(b1));
}

__device__ __forceinline__ void cp16(uint32_t sdst, const float* gsrc) {
    asm volatile("cp.async.cg.shared.global [%0], [%1], 16;" :: "r"(sdst), "l"(gsrc));
}

// phi expansion: x[16] -> 160 features written dst[f*132 + tok] (raw fp32 bits)
__device__ __forceinline__ void write_phi_colmajor(uint32_t* dst, int tok, const float* xf) {
    float x[16];
    #pragma unroll
    for (int i = 0; i < 16; i++) x[i] = xf[i];
    dst[tok] = 0x3f800000u;
    #pragma unroll
    for (int i = 0; i < 16; i++) dst[(1 + i) * 132 + tok] = __float_as_uint(x[i]);
    const float inv = 0.70710678118654752440f;
    int idx = 17;
    #pragma unroll
    for (int i = 0; i < 16; i++) {
        dst[idx * 132 + tok] = __float_as_uint(0.5f * x[i] * x[i]); idx++;
        #pragma unroll
        for (int j = i + 1; j < 16; j++) {
            dst[idx * 132 + tok] = __float_as_uint(inv * x[i] * x[j]); idx++;
        }
    }
    #pragma unroll
    for (int f = FDIM; f < FPAD; f++) dst[f * 132 + tok] = 0u;
}

__device__ __forceinline__ void write_phi_rowmajor(uint32_t* dst, const float* xf) {
    float x[16];
    #pragma unroll
    for (int i = 0; i < 16; i++) x[i] = xf[i];
    dst[0] = 0x3f800000u;
    #pragma unroll
    for (int i = 0; i < 16; i++) dst[1 + i] = __float_as_uint(x[i]);
    const float inv = 0.70710678118654752440f;
    int idx = 17;
    #pragma unroll
    for (int i = 0; i < 16; i++) {
        dst[idx++] = __float_as_uint(0.5f * x[i] * x[i]);
        #pragma unroll
        for (int j = i + 1; j < 16; j++)
            dst[idx++] = __float_as_uint(inv * x[i] * x[j]);
    }
    #pragma unroll
    for (int f = FDIM; f < FPAD; f++) dst[f] = 0u;
}

// ------------------------------- RMSNorm (float4) -----------------------------
__global__ void rmsnorm_kernel(const float* __restrict__ x,
                               const float* __restrict__ w,
                               float* __restrict__ h) {
    int row = blockIdx.x;
    const float4* xr = (const float4*)(x + (size_t)row * DMODEL);
    float4 t = xr[threadIdx.x];
    float s = t.x * t.x + t.y * t.y + t.z * t.z + t.w * t.w;
    __shared__ float red[8];
    #pragma unroll
    for (int o = 16; o > 0; o >>= 1) s += __shfl_xor_sync(0xffffffffu, s, o);
    if ((threadIdx.x & 31) == 0) red[threadIdx.x >> 5] = s;
    __syncthreads();
    if (threadIdx.x < 8) {
        float v = red[threadIdx.x];
        #pragma unroll
        for (int o = 4; o > 0; o >>= 1) v += __shfl_xor_sync(0xffu, v, o);
        if (threadIdx.x == 0) red[0] = v;
    }
    __syncthreads();
    float rs = rsqrtf(red[0] / (float)DMODEL + 1e-6f);
    float4 wv = ((const float4*)w)[threadIdx.x];
    float4 o;
    o.x = t.x * rs * wv.x; o.y = t.y * rs * wv.y;
    o.z = t.z * rs * wv.z; o.w = t.w * rs * wv.w;
    ((float4*)(h + (size_t)row * DMODEL))[threadIdx.x] = o;
}

// -------------- TF32 GEMM: cp.async 3-stage, k-tile 32, raw-bit tf32 ----------
#define AS_ELE (128*36)
#define BS_ELE (32*136)
#define NSTAGE 3

__device__ __forceinline__ void gemm_issue(const float* A, const float* B,
        float* As, float* Bs, int bm, int bn, int k0, int K, int N, int tid) {
    #pragma unroll
    for (int j = 0; j < 4; j++) {
        int c = tid + j * 256;            // 1024 float4 chunks of A (128 x 32)
        int m = c >> 3, seg = c & 7;
        cp16((uint32_t)__cvta_generic_to_shared(As + m * 36 + seg * 4),
             A + (size_t)(bm + m) * K + k0 + seg * 4);
    }
    #pragma unroll
    for (int j = 0; j < 4; j++) {
        int c = tid + j * 256;            // 1024 float4 chunks of B (32 x 128)
        int kk = c >> 5, nc = c & 31;
        cp16((uint32_t)__cvta_generic_to_shared(Bs + kk * 136 + nc * 4),
             B + (size_t)(k0 + kk) * N + bn + nc * 4);
    }
}

__device__ __forceinline__ void gemm_core(const float* A, const float* B, float* C,
        const float* residual, float* As, float* Bs, int bm, int bn, int K, int N,
        int tid) {
    int warp = tid >> 5, lane = tid & 31;
    int wm = (warp >> 2) * 64, wn = (warp & 3) * 32;
    int r = lane >> 2, cq = lane & 3;

    float acc[4][4][4];
    #pragma unroll
    for (int mi = 0; mi < 4; mi++)
        #pragma unroll
        for (int ni = 0; ni < 4; ni++)
            #pragma unroll
            for (int e = 0; e < 4; e++) acc[mi][ni][e] = 0.f;

    int nk = K / 32;
    gemm_issue(A, B, As, Bs, bm, bn, 0, K, N, tid);
    asm volatile("cp.async.commit_group;");
    gemm_issue(A, B, As + AS_ELE, Bs + BS_ELE, bm, bn, 32, K, N, tid);
    asm volatile("cp.async.commit_group;");

    for (int kt = 0; kt < nk; kt++) {
        if (kt + 2 < nk) {
            int slot = (kt + 2) % 3;
            gemm_issue(A, B, As + slot * AS_ELE, Bs + slot * BS_ELE,
                       bm, bn, (kt + 2) * 32, K, N, tid);
        }
        asm volatile("cp.async.commit_group;");
        asm volatile("cp.async.wait_group 2;");
        __syncthreads();
        const uint32_t* Au = (const uint32_t*)(As + (kt % 3) * AS_ELE);
        const uint32_t* Bu = (const uint32_t*)(Bs + (kt % 3) * BS_ELE);
        #pragma unroll
        for (int ks = 0; ks < 32; ks += 8) {
            uint32_t af[4][4], bf[4][2];
            #pragma unroll
            for (int mi = 0; mi < 4; mi++) {
                int m = wm + mi * 16 + r;
                af[mi][0] = Au[m * 36 + ks + cq];
                af[mi][1] = Au[(m + 8) * 36 + ks + cq];
                af[mi][2] = Au[m * 36 + ks + cq + 4];
                af[mi][3] = Au[(m + 8) * 36 + ks + cq + 4];
            }
            #pragma unroll
            for (int ni = 0; ni < 4; ni++) {
                int n = wn + ni * 8 + r;
                bf[ni][0] = Bu[(ks + cq) * 136 + n];
                bf[ni][1] = Bu[(ks + cq + 4) * 136 + n];
            }
            #pragma unroll
            for (int mi = 0; mi < 4; mi++)
                #pragma unroll
                for (int ni = 0; ni < 4; ni++)
                    mma8(acc[mi][ni], af[mi][0], af[mi][1], af[mi][2], af[mi][3],
                         bf[ni][0], bf[ni][1]);
        }
        __syncthreads();
    }

    #pragma unroll
    for (int mi = 0; mi < 4; mi++) {
        int row0 = bm + wm + mi * 16 + r;
        #pragma unroll
        for (int ni = 0; ni < 4; ni++) {
            int col = bn + wn + ni * 8 + 2 * cq;
            float2 lo = make_float2(acc[mi][ni][0], acc[mi][ni][1]);
            float2 hi = make_float2(acc[mi][ni][2], acc[mi][ni][3]);
            if (residual) {
                float2 r0 = *(const float2*)(residual + (size_t)row0 * N + col);
                float2 r1 = *(const float2*)(residual + (size_t)(row0 + 8) * N + col);
                lo.x += r0.x; lo.y += r0.y; hi.x += r1.x; hi.y += r1.y;
            }
            *(float2*)(C + (size_t)row0 * N + col) = lo;
            *(float2*)(C + (size_t)(row0 + 8) * N + col) = hi;
        }
    }
}

__global__ __launch_bounds__(256) void gemm_v2(
        const float* __restrict__ A, const float* __restrict__ B,
        float* __restrict__ C, const float* __restrict__ residual,
        int M, int N, int K) {
    extern __shared__ float sg[];
    gemm_core(A, B, C, residual, sg, sg + NSTAGE * AS_ELE,
              blockIdx.y * 128, blockIdx.x * 128, K, N, threadIdx.x);
}

__global__ __launch_bounds__(256) void gemm_qkv(
        const float* __restrict__ A,
        const float* __restrict__ Bq, const float* __restrict__ Bk,
        const float* __restrict__ Bv,
        float* __restrict__ Cq, float* __restrict__ Ck, float* __restrict__ Cv) {
    extern __shared__ float sg[];
    const float* B = (blockIdx.z == 0) ? Bq : (blockIdx.z == 1) ? Bk : Bv;
    float* C = (blockIdx.z == 0) ? Cq : (blockIdx.z == 1) ? Ck : Cv;
    gemm_core(A, B, C, nullptr, sg, sg + NSTAGE * AS_ELE,
              blockIdx.y * 128, blockIdx.x * 128, DMODEL, DMODEL, threadIdx.x);
}

// --------- pass A: fused feat-proj + phi + KV' = Kphi^T @ [V|1] ---------------
__global__ __launch_bounds__(320) void chunk_kv_v3(const float* __restrict__ kk_,
        const float* __restrict__ vv, const float* __restrict__ Wkf,
        float* __restrict__ ckv) {
    extern __shared__ uint32_t su[];
    uint32_t* Ks = su;              // [tok 128][feat 164]
    uint32_t* Vs = su + 128 * 164;  // [tok 128][88]
    float* Kf = (float*)Ks;         // overlay: raw k tile [128][68]
    float* Sf = (float*)Vs;         // overlay: W [1024] + kf [2048]
    int tid = threadIdx.x, warp = tid >> 5, lane = tid & 31;
    int r = lane >> 2, cq = lane & 3;
    int bhc = blockIdx.x, c = bhc & 15, bh = bhc >> 4, b = bh >> 4, hh = bh & 15;
    size_t row0 = (size_t)(b * SEQ + c * CHUNKSZ) * DMODEL + hh * HD;

    for (int i = tid; i < 128 * 16; i += 320) {
        int tok = i >> 4, qd = (i & 15) * 4;
        float4 t = *(const float4*)(kk_ + row0 + (size_t)tok * DMODEL + qd);
        *(float4*)(Kf + tok * 68 + qd) = t;
    }
    for (int i = tid; i < 1024; i += 320) Sf[i] = Wkf[i];
    __syncthreads();

    if (tid < 128) {
        int tok = tid;
        float accf[16];
        #pragma unroll
        for (int cc = 0; cc < 16; cc++) accf[cc] = 0.f;
        for (int e = 0; e < 64; e++) {
            float rv = Kf[tok * 68 + e];
            #pragma unroll
            for (int cc = 0; cc < 16; cc++) accf[cc] += rv * Sf[e * 16 + cc];
        }
        #pragma unroll
        for (int cc = 0; cc < 16; cc++) Sf[1024 + tok * 16 + cc] = accf[cc];
    }
    __syncthreads();
    if (tid < 128) write_phi_rowmajor(Ks + tid * 164, Sf + 1024 + tid * 16);
    __syncthreads();

    for (int i = tid; i < 128 * 18; i += 320) {
        int tok = i / 18, qd = (i % 18) * 4;
        uint4 u = make_uint4(0u, 0u, 0u, 0u);
        if (qd < 64) {
            float4 t = *(const float4*)(vv + row0 + (size_t)tok * DMODEL + qd);
            u = make_uint4(__float_as_uint(t.x), __float_as_uint(t.y),
                           __float_as_uint(t.z), __float_as_uint(t.w));
        } else if (qd == 64) u.x = 0x3f800000u;
        *(uint4*)(Vs + tok * 88 + qd) = u;
    }
    __syncthreads();

    float acc[9][4];
    #pragma unroll
    for (int ni = 0; ni < 9; ni++)
        #pragma unroll
        for (int e = 0; e < 4; e++) acc[ni][e] = 0.f;
    int m0 = warp * 16;
    for (int kk = 0; kk < 128; kk += 8) {
        uint32_t a0 = Ks[(kk + cq) * 164 + m0 + r];
        uint32_t a1 = Ks[(kk + cq) * 164 + m0 + r + 8];
        uint32_t a2 = Ks[(kk + cq + 4) * 164 + m0 + r];
        uint32_t a3 = Ks[(kk + cq + 4) * 164 + m0 + r + 8];
        #pragma unroll
        for (int ni = 0; ni < 9; ni++) {
            uint32_t b0 = Vs[(kk + cq) * 88 + ni * 8 + r];
            uint32_t b1 = Vs[(kk + cq + 4) * 88 + ni * 8 + r];
            mma8(acc[ni], a0, a1, a2, a3, b0, b1);
        }
    }
    float* outb = ckv + (size_t)bhc * FPAD * 72;
    #pragma unroll
    for (int ni = 0; ni < 9; ni++) {
        int n = ni * 8 + 2 * cq;
        *(float2*)(outb + (m0 + r) * 72 + n)     = make_float2(acc[ni][0], acc[ni][1]);
        *(float2*)(outb + (m0 + r + 8) * 72 + n) = make_float2(acc[ni][2], acc[ni][3]);
    }
}

// --------------------- pass B: exclusive prefix over chunks ------------------
__global__ void prefix_kv_v2(float* __restrict__ ckv) {
    const int FD = FPAD * 72;
    int idx = blockIdx.x * 256 + threadIdx.x;
    if (idx >= 32 * FD) return;
    int bh = idx / FD, e = idx % FD;
    size_t base = (size_t)bh * NCHUNK * FD + e;
    float run = 0.f;
    for (int c = 0; c < NCHUNK; c++) {
        float cur = ckv[base + (size_t)c * FD];
        ckv[base + (size_t)c * FD] = run;
        run += cur;
    }
}

// --------- pass C: fused feat-proj + phi + linear attention (tf32) ------------
__global__ __launch_bounds__(256) void lin_attn_v4(const float* __restrict__ qq_,
        const float* __restrict__ kk_, const float* __restrict__ vv,
        const float* __restrict__ Wqf, const float* __restrict__ Wkf,
        const float* __restrict__ ckv, float* __restrict__ cat) {
    extern __shared__ uint32_t su[];
    uint32_t* Qs  = su;                    // [k 160][m 132]
    uint32_t* Ks  = su + 160 * 132;        // [k 160][n 132]
    uint32_t* KVs = Ks + 160 * 132;        // [k 160][n 88]
    uint32_t* Am  = Ks;                    // overlay
    uint32_t* Vs  = Ks + 128 * 132;        // overlay
    float* Qraw = (float*)Qs;              // [128][68]
    float* Kraw = (float*)Ks;              // [128][68]
    float* Scr  = (float*)KVs;
    int tid = threadIdx.x, warp = tid >> 5, lane = tid & 31;
    int r = lane >> 2, cq = lane & 3;
    int bhc = blockIdx.x, c = bhc & 15, bh = bhc >> 4, b = bh >> 4, hh = bh & 15;
    size_t row0 = (size_t)(b * SEQ + c * CHUNKSZ) * DMODEL + hh * HD;

    for (int i = tid; i < 128 * 16; i += 256) {
        int tok = i >> 4, qd = (i & 15) * 4;
        *(float4*)(Qraw + tok * 68 + qd) =
            *(const float4*)(qq_ + row0 + (size_t)tok * DMODEL + qd);
        *(float4*)(Kraw + tok * 68 + qd) =
            *(const float4*)(kk_ + row0 + (size_t)tok * DMODEL + qd);
    }
    for (int i = tid; i < 1024; i += 256) { Scr[i] = Wqf[i]; Scr[1024 + i] = Wkf[i]; }
    __syncthreads();

    {
        int tok = tid & 127, which = tid >> 7;
        const float* raw = which ? Kraw : Qraw;
        const float* W   = Scr + which * 1024;
        float* of        = Scr + 2048 + which * 2048;
        float accf[16];
        #pragma unroll
        for (int cc = 0; cc < 16; cc++) accf[cc] = 0.f;
        for (int e = 0; e < 64; e++) {
            float rv = raw[tok * 68 + e];
            #pragma unroll
            for (int cc = 0; cc < 16; cc++) accf[cc] += rv * W[e * 16 + cc];
        }
        #pragma unroll
        for (int cc = 0; cc < 16; cc++) of[tok * 16 + cc] = accf[cc];
    }
    __syncthreads();
    {
        int tok = tid & 127, which = tid >> 7;
        uint32_t* dst = which ? Ks : Qs;
        write_phi_colmajor(dst, tok, Scr + 2048 + which * 2048 + tok * 16);
    }
    __syncthreads();

    const float* kvb = ckv + (size_t)bhc * FPAD * 72;
    for (int i = tid; i < 160 * 36; i += 256) {
        int f = i / 36, n = (i % 36) * 2;
        float2 t = *(const float2*)(kvb + f * 72 + n);
        KVs[f * 88 + n]     = __float_as_uint(t.x);
        KVs[f * 88 + n + 1] = __float_as_uint(t.y);
    }
    __syncthreads();

    float accy[9][4];
    #pragma unroll
    for (int ni = 0; ni < 9; ni++)
        #pragma unroll
        for (int e = 0; e < 4; e++) accy[ni][e] = 0.f;
    int m0 = warp * 16;
    for (int kk = 0; kk < 160; kk += 8) {
        uint32_t a0 = Qs[(kk + cq) * 132 + m0 + r];
        uint32_t a1 = Qs[(kk + cq) * 132 + m0 + r + 8];
        uint32_t a2 = Qs[(kk + cq + 4) * 132 + m0 + r];
        uint32_t a3 = Qs[(kk + cq + 4) * 132 + m0 + r + 8];
        #pragma unroll
        for (int ni = 0; ni < 9; ni++) {
            uint32_t b0 = KVs[(kk + cq) * 88 + ni * 8 + r];
            uint32_t b1 = KVs[(kk + cq + 4) * 88 + ni * 8 + r];
            mma8(accy[ni], a0, a1, a2, a3, b0, b1);
        }
    }

    float acc1[4][4][4];
    #pragma unroll
    for (int mi = 0; mi < 4; mi++)
        #pragma unroll
        for (int ni = 0; ni < 4; ni++)
            #pragma unroll
            for (int e = 0; e < 4; e++) acc1[mi][ni][e] = 0.f;
    int wm = (warp >> 2) * 64, wn = (warp & 3) * 32;
    for (int kk = 0; kk < 160; kk += 8) {
        uint32_t af[4][4];
        #pragma unroll
        for (int mi = 0; mi < 4; mi++) {
            int m = wm + mi * 16;
            af[mi][0] = Qs[(kk + cq) * 132 + m + r];
            af[mi][1] = Qs[(kk + cq) * 132 + m + r + 8];
            af[mi][2] = Qs[(kk + cq + 4) * 132 + m + r];
            af[mi][3] = Qs[(kk + cq + 4) * 132 + m + r + 8];
        }
        #pragma unroll
        for (int ni = 0; ni < 4; ni++) {
            uint32_t b0 = Ks[(kk + cq) * 132 + wn + ni * 8 + r];
            uint32_t b1 = Ks[(kk + cq + 4) * 132 + wn + ni * 8 + r];
            #pragma unroll
            for (int mi = 0; mi < 4; mi++)
                mma8(acc1[mi][ni], af[mi][0], af[mi][1], af[mi][2], af[mi][3], b0, b1);
        }
    }
    __syncthreads();

    #pragma unroll
    for (int mi = 0; mi < 4; mi++) {
        int row = wm + mi * 16 + r;
        #pragma unroll
        for (int ni = 0; ni < 4; ni++) {
            int col = wn + ni * 8 + 2 * cq;
            Am[col * 132 + row]           = (col     <= row)     ? __float_as_uint(acc1[mi][ni][0]) : 0u;
            Am[(col + 1) * 132 + row]     = (col + 1 <= row)     ? __float_as_uint(acc1[mi][ni][1]) : 0u;
            Am[col * 132 + row + 8]       = (col     <= row + 8) ? __float_as_uint(acc1[mi][ni][2]) : 0u;
            Am[(col + 1) * 132 + row + 8] = (col + 1 <= row + 8) ? __float_as_uint(acc1[mi][ni][3]) : 0u;
        }
    }
    for (int i = tid; i < 128 * 18; i += 256) {
        int tok = i / 18, qd = (i % 18) * 4;
        uint4 u = make_uint4(0u, 0u, 0u, 0u);
        if (qd < 64) {
            float4 t = *(const float4*)(vv + row0 + (size_t)tok * DMODEL + qd);
            u = make_uint4(__float_as_uint(t.x), __float_as_uint(t.y),
                           __float_as_uint(t.z), __float_as_uint(t.w));
        } else if (qd == 64) u.x = 0x3f800000u;
        *(uint4*)(Vs + tok * 88 + qd) = u;
    }
    __syncthreads();

    for (int kk = 0; kk < 128; kk += 8) {
        uint32_t a0 = Am[(kk + cq) * 132 + m0 + r];
        uint32_t a1 = Am[(kk + cq) * 132 + m0 + r + 8];
        uint32_t a2 = Am[(kk + cq + 4) * 132 + m0 + r];
        uint32_t a3 = Am[(kk + cq + 4) * 132 + m0 + r + 8];
        #pragma unroll
        for (int ni = 0; ni < 9; ni++) {
            uint32_t b0 = Vs[(kk + cq) * 88 + ni * 8 + r];
            uint32_t b1 = Vs[(kk + cq + 4) * 88 + ni * 8 + r];
            mma8(accy[ni], a0, a1, a2, a3, b0, b1);
        }
    }

    float zlo = __shfl_sync(0xffffffffu, accy[8][0], lane & 28) + 1e-6f;
    float zhi = __shfl_sync(0xffffffffu, accy[8][2], lane & 28) + 1e-6f;
    float izlo = 1.f / zlo, izhi = 1.f / zhi;
    size_t rowg = (size_t)(b * SEQ + c * CHUNKSZ + m0 + r);
    #pragma unroll
    for (int ni = 0; ni < 8; ni++) {
        int colg = hh * HD + ni * 8 + 2 * cq;
        *(float2*)(cat + rowg * (2 * DMODEL) + colg) =
            make_float2(accy[ni][0] * izlo, accy[ni][1] * izlo);
        *(float2*)(cat + (rowg + 8) * (2 * DMODEL) + colg) =
            make_float2(accy[ni][2] * izhi, accy[ni][3] * izhi);
    }
}

// ---------------- sliding-window attention (256 thr, warp-pair) --------------
__global__ __launch_bounds__(256) void swa_v4(const float* __restrict__ q,
        const float* __restrict__ k, const float* __restrict__ v,
        float* __restrict__ cat) {
    extern __shared__ uint32_t su[];
    uint32_t* Qs = su;               // [e 64][tok 68]
    uint32_t* Ks = Qs + 64 * 68;     // [e 64][key 132]
    uint32_t* Ps = Ks + 64 * 132;    // [key 128][tok 68]
    uint32_t* Vs = Ps + 128 * 68;    // [key 128][d 68]
    float* red   = (float*)(Vs + 128 * 68);
    float* Osm   = (float*)Qs;       // overlay after S phase
    int tid = threadIdx.x, warp = tid >> 5, lane = tid & 31;
    int r = lane >> 2, cq = lane & 3;
    int g = warp & 3, half = warp >> 2;
    int m0 = g * 16;
    int q0 = blockIdx.x * 64, hh = blockIdx.y, b = blockIdx.z;

    for (int i = tid; i < 64 * 16; i += 256) {
        int tok = i >> 4, qd = (i & 15) * 4;
        float4 t = *(const float4*)(q + (size_t)(b * SEQ + q0 + tok) * DMODEL + hh * HD + qd);
        Qs[(qd + 0) * 68 + tok] = __float_as_uint(t.x);
        Qs[(qd + 1) * 68 + tok] = __float_as_uint(t.y);
        Qs[(qd + 2) * 68 + tok] = __float_as_uint(t.z);
        Qs[(qd + 3) * 68 + tok] = __float_as_uint(t.w);
    }
    for (int i = tid; i < 128 * 16; i += 256) {
        int key = i >> 4, qd = (i & 15) * 4;
        int kg = q0 - 64 + key;
        float4 tk = make_float4(0.f, 0.f, 0.f, 0.f);
        float4 tv = make_float4(0.f, 0.f, 0.f, 0.f);
        if (kg >= 0) {
            tk = *(const float4*)(k + (size_t)(b * SEQ + kg) * DMODEL + hh * HD + qd);
            tv = *(const float4*)(v + (size_t)(b * SEQ + kg) * DMODEL + hh * HD + qd);
        }
        Ks[(qd + 0) * 132 + key] = __float_as_uint(tk.x);
        Ks[(qd + 1) * 132 + key] = __float_as_uint(tk.y);
        Ks[(qd + 2) * 132 + key] = __float_as_uint(tk.z);
        Ks[(qd + 3) * 132 + key] = __float_as_uint(tk.w);
        *(uint4*)(Vs + key * 68 + qd) =
            make_uint4(__float_as_uint(tv.x), __float_as_uint(tv.y),
                       __float_as_uint(tv.z), __float_as_uint(tv.w));
    }
    __syncthreads();

    float acc[8][4];
    #pragma unroll
    for (int ni = 0; ni < 8; ni++)
        #pragma unroll
        for (int e = 0; e < 4; e++) acc[ni][e] = 0.f;
    for (int kk = 0; kk < 64; kk += 8) {
        uint32_t a0 = Qs[(kk + cq) * 68 + m0 + r];
        uint32_t a1 = Qs[(kk + cq) * 68 + m0 + r + 8];
        uint32_t a2 = Qs[(kk + cq + 4) * 68 + m0 + r];
        uint32_t a3 = Qs[(kk + cq + 4) * 68 + m0 + r + 8];
        #pragma unroll
        for (int ni = 0; ni < 8; ni++) {
            int gn = half * 8 + ni;
            uint32_t b0 = Ks[(kk + cq) * 132 + gn * 8 + r];
            uint32_t b1 = Ks[(kk + cq + 4) * 132 + gn * 8 + r];
            mma8(acc[ni], a0, a1, a2, a3, b0, b1);
        }
    }

    int rowlo = m0 + r, rowhi = rowlo + 8;
    float mlo = -1e30f, mhi = -1e30f;
    #pragma unroll
    for (int ni = 0; ni < 8; ni++) {
        int n = (half * 8 + ni) * 8 + 2 * cq;
        bool ok0l = (n     >= rowlo) && (n     <= rowlo + 64) && (q0 - 64 + n     >= 0);
        bool ok1l = (n + 1 >= rowlo) && (n + 1 <= rowlo + 64) && (q0 - 64 + n + 1 >= 0);
        bool ok0h = (n     >= rowhi) && (n     <= rowhi + 64) && (q0 - 64 + n     >= 0);
        bool ok1h = (n + 1 >= rowhi) && (n + 1 <= rowhi + 64) && (q0 - 64 + n + 1 >= 0);
        acc[ni][0] = ok0l ? acc[ni][0] * 0.125f : -1e30f;
        acc[ni][1] = ok1l ? acc[ni][1] * 0.125f : -1e30f;
        acc[ni][2] = ok0h ? acc[ni][2] * 0.125f : -1e30f;
        acc[ni][3] = ok1h ? acc[ni][3] * 0.125f : -1e30f;
        mlo = fmaxf(mlo, fmaxf(acc[ni][0], acc[ni][1]));
        mhi = fmaxf(mhi, fmaxf(acc[ni][2], acc[ni][3]));
    }
    mlo = fmaxf(mlo, __shfl_xor_sync(0xffffffffu, mlo, 1));
    mlo = fmaxf(mlo, __shfl_xor_sync(0xffffffffu, mlo, 2));
    mhi = fmaxf(mhi, __shfl_xor_sync(0xffffffffu, mhi, 1));
    mhi = fmaxf(mhi, __shfl_xor_sync(0xffffffffu, mhi, 2));
    if (cq == 0) {
        red[rowlo * 2 + half] = mlo;
        red[rowhi * 2 + half] = mhi;
    }
    __syncthreads();
    float Mlo = fmaxf(red[rowlo * 2], red[rowlo * 2 + 1]);
    float Mhi = fmaxf(red[rowhi * 2], red[rowhi * 2 + 1]);

    float slo = 0.f, shi = 0.f;
    #pragma unroll
    for (int ni = 0; ni < 8; ni++) {
        acc[ni][0] = __expf(acc[ni][0] - Mlo);
        acc[ni][1] = __expf(acc[ni][1] - Mlo);
        acc[ni][2] = __expf(acc[ni][2] - Mhi);
        acc[ni][3] = __expf(acc[ni][3] - Mhi);
        slo += acc[ni][0] + acc[ni][1];
        shi += acc[ni][2] + acc[ni][3];
    }
    slo += __shfl_xor_sync(0xffffffffu, slo, 1);
    slo += __shfl_xor_sync(0xffffffffu, slo, 2);
    shi += __shfl_xor_sync(0xffffffffu, shi, 1);
    shi += __shfl_xor_sync(0xffffffffu, shi, 2);
    if (cq == 0) {
        red[128 + rowlo * 2 + half] = slo;
        red[128 + rowhi * 2 + half] = shi;
    }

    #pragma unroll
    for (int ni = 0; ni < 8; ni++) {
        int n = (half * 8 + ni) * 8 + 2 * cq;
        Ps[n * 68 + rowlo]       = __float_as_uint(acc[ni][0]);
        Ps[(n + 1) * 68 + rowlo] = __float_as_uint(acc[ni][1]);
        Ps[n * 68 + rowhi]       = __float_as_uint(acc[ni][2]);
        Ps[(n + 1) * 68 + rowhi] = __float_as_uint(acc[ni][3]);
    }
    __syncthreads();
    float sumlo = red[128 + rowlo * 2] + red[128 + rowlo * 2 + 1];
    float sumhi = red[128 + rowhi * 2] + red[128 + rowhi * 2 + 1];

    float accO[8][4];
    #pragma unroll
    for (int ni = 0; ni < 8; ni++)
        #pragma unroll
        for (int e = 0; e < 4; e++) accO[ni][e] = 0.f;
    for (int ks = 0; ks < 64; ks += 8) {
        int kk = half * 64 + ks;
        uint32_t a0 = Ps[(kk + cq) * 68 + m0 + r];
        uint32_t a1 = Ps[(kk + cq) * 68 + m0 + r + 8];
        uint32_t a2 = Ps[(kk + cq + 4) * 68 + m0 + r];
        uint32_t a3 = Ps[(kk + cq + 4) * 68 + m0 + r + 8];
        #pragma unroll
        for (int ni = 0; ni < 8; ni++) {
            uint32_t b0 = Vs[(kk + cq) * 68 + ni * 8 + r];
            uint32_t b1 = Vs[(kk + cq + 4) * 68 + ni * 8 + r];
            mma8(accO[ni], a0, a1, a2, a3, b0, b1);
        }
    }
    if (half == 1) {
        #pragma unroll
        for (int ni = 0; ni < 8; ni++) {
            int n = ni * 8 + 2 * cq;
            Osm[rowlo * 68 + n]     = accO[ni][0];
            Osm[rowlo * 68 + n + 1] = accO[ni][1];
            Osm[rowhi * 68 + n]     = accO[ni][2];
            Osm[rowhi * 68 + n + 1] = accO[ni][3];
        }
    }
    __syncthreads();
    if (half == 0) {
        float izlo = 1.f / sumlo, izhi = 1.f / sumhi;
        #pragma unroll
        for (int ni = 0; ni < 8; ni++) {
            int n = ni * 8 + 2 * cq;
            int colg = DMODEL + hh * HD + n;
            *(float2*)(cat + (size_t)(b * SEQ + q0 + rowlo) * (2 * DMODEL) + colg) =
                make_float2((accO[ni][0] + Osm[rowlo * 68 + n]) * izlo,
                            (accO[ni][1] + Osm[rowlo * 68 + n + 1]) * izlo);
            *(float2*)(cat + (size_t)(b * SEQ + q0 + rowhi) * (2 * DMODEL) + colg) =
                make_float2((accO[ni][2] + Osm[rowhi * 68 + n]) * izhi,
                            (accO[ni][3] + Osm[rowhi * 68 + n + 1]) * izhi);
        }
    }
}

// ---------------------------------- launch -----------------------------------
extern "C" void kernel_launch(void* const* d_in, const int* in_sizes, int n_in,
                              void* d_out, int out_size) {
    const float* x      = (const float*)d_in[0];
    const float* norm_w = (const float*)d_in[1];
    const float* Wq     = (const float*)d_in[2];
    const float* Wk     = (const float*)d_in[3];
    const float* Wv     = (const float*)d_in[4];
    const float* Wqf    = (const float*)d_in[5];
    const float* Wkf    = (const float*)d_in[6];
    const float* Wout   = (const float*)d_in[7];
    float* out = (float*)d_out;

    float *h, *q, *k, *v, *ckv, *cat;
    cudaGetSymbolAddress((void**)&h,   g_h);
    cudaGetSymbolAddress((void**)&q,   g_q);
    cudaGetSymbolAddress((void**)&k,   g_k);
    cudaGetSymbolAddress((void**)&v,   g_v);
    cudaGetSymbolAddress((void**)&ckv, g_ckv);
    cudaGetSymbolAddress((void**)&cat, g_cat);

    const int smemG   = NSTAGE * (AS_ELE + BS_ELE) * 4;                 // 107520
    const int smemKV  = (128 * 164 + 128 * 88) * 4;                     // 129024
    const int smemLin = (160 * 132 + 160 * 132 + 160 * 88) * 4;         // 225280
    const int smemSWA = (64 * 68 + 64 * 132 + 128 * 68 + 128 * 68) * 4 + 256 * 4;

    static cudaStream_t s2 = nullptr;
    static cudaEvent_t ev_fork = nullptr, ev_join = nullptr;
    static bool attrs_set = false;
    if (!attrs_set) {
        cudaFuncSetAttribute(gemm_v2,     cudaFuncAttributeMaxDynamicSharedMemorySize, smemG);
        cudaFuncSetAttribute(gemm_qkv,    cudaFuncAttributeMaxDynamicSharedMemorySize, smemG);
        cudaFuncSetAttribute(chunk_kv_v3, cudaFuncAttributeMaxDynamicSharedMemorySize, smemKV);
        cudaFuncSetAttribute(lin_attn_v4, cudaFuncAttributeMaxDynamicSharedMemorySize, smemLin);
        cudaFuncSetAttribute(swa_v4,      cudaFuncAttributeMaxDynamicSharedMemorySize, smemSWA);
        cudaStreamCreateWithFlags(&s2, cudaStreamNonBlocking);
        cudaEventCreateWithFlags(&ev_fork, cudaEventDisableTiming);
        cudaEventCreateWithFlags(&ev_join, cudaEventDisableTiming);
        attrs_set = true;
    }

    rmsnorm_kernel<<<ROWS, 256>>>(x, norm_w, h);

    gemm_qkv<<<dim3(DMODEL / 128, ROWS / 128, 3), 256, smemG>>>(h, Wq, Wk, Wv, q, k, v);

    // fork: SWA runs concurrently with the linear-attention chain
    cudaEventRecord(ev_fork, 0);
    cudaStreamWaitEvent(s2, ev_fork, 0);
    swa_v4<<<dim3(SEQ / 64, NH, BATCH), 256, smemSWA, s2>>>(q, k, v, cat);
    cudaEventRecord(ev_join, s2);

    chunk_kv_v3<<<BATCH * NH * NCHUNK, 320, smemKV>>>(k, v, Wkf, ckv);
    prefix_kv_v2<<<(32 * FPAD * 72 + 255) / 256, 256>>>(ckv);
    lin_attn_v4<<<BATCH * NH * NCHUNK, 256, smemLin>>>(q, k, v, Wqf, Wkf, ckv, cat);

    // join before the output GEMM consumes cat
    cudaStreamWaitEvent(0, ev_join, 0);

    gemm_v2<<<dim3(DMODEL / 128, ROWS / 128), 256, smemG>>>(cat, Wout, out, x, ROWS, DMODEL, 2 * DMODEL);
}